// round 1
// baseline (speedup 1.0000x reference)
#include <cuda_runtime.h>
#include <cuda_bf16.h>
#include <math.h>

// Problem constants
#define NN 100000
#define FF 512
#define HH 128
#define HH2 256
#define EE 1600000
#define CC 64
#define NFf 100000.0f
#define LN_EPS 1e-5f
#define GW 0.8f

// ---------------- scratch (device globals; allocation-free) ----------------
__device__ float g_scratch[(size_t)NN * HH2];  // pre-activations, then attn "num"
__device__ float g_ht[(size_t)NN * HH];
__device__ float g_hg[(size_t)NN * HH];
__device__ float g_q[(size_t)NN * HH2];
__device__ float g_k[(size_t)NN * HH2];
__device__ float g_v[(size_t)NN * HH2];
__device__ float g_x1[(size_t)NN * HH];
__device__ float g_agg[(size_t)NN * HH];
__device__ float g_y[(size_t)NN * HH];
__device__ float g_deg[NN];
__device__ float g_val[EE];
__device__ float g_kvs[2 * HH * HH];
__device__ float g_red[2];     // sum q^2, sum k^2
__device__ float g_ksum[HH2];  // column sums of k

// ---------------- utility ----------------
__global__ void zero_kernel(float* p, size_t n) {
    size_t i = (size_t)blockIdx.x * blockDim.x + threadIdx.x;
    size_t stride = (size_t)gridDim.x * blockDim.x;
    for (; i < n; i += stride) p[i] = 0.0f;
}

// block of 128 threads reduction
__device__ __forceinline__ float blockReduce128(float v, volatile float* sh) {
    unsigned m = 0xffffffffu;
    v += __shfl_down_sync(m, v, 16);
    v += __shfl_down_sync(m, v, 8);
    v += __shfl_down_sync(m, v, 4);
    v += __shfl_down_sync(m, v, 2);
    v += __shfl_down_sync(m, v, 1);
    int lane = threadIdx.x & 31, warp = threadIdx.x >> 5;
    if (lane == 0) sh[warp] = v;
    __syncthreads();
    float r = sh[0] + sh[1] + sh[2] + sh[3];
    __syncthreads();
    return r;
}

// ---------------- generic tiled SGEMM: C[M,N] = A[M,K]@B[K,N] (+bias) ----------------
// BM=64, BN=64, BK=16, 256 threads, 4x4 micro-tile.
// Requires: K % 16 == 0, N % 64 == 0, 16B alignment of A/B rows (true for all calls here).
__global__ void sgemm_kernel(const float* __restrict__ A, int lda,
                             const float* __restrict__ B, int ldb,
                             const float* __restrict__ bias,
                             float* __restrict__ C, int ldc,
                             int M, int N, int K) {
    __shared__ __align__(16) float As[16][68];
    __shared__ __align__(16) float Bs[16][64];
    int tid = threadIdx.x;
    int bm = blockIdx.y * 64, bn = blockIdx.x * 64;
    int tr = tid >> 4, tc = tid & 15;

    float acc[4][4] = {};

    int a_row = tid >> 2;
    int a_k = (tid & 3) * 4;
    int b_row = tid >> 4;
    int b_c = (tid & 15) * 4;
    int m_a = bm + a_row;

    for (int k0 = 0; k0 < K; k0 += 16) {
        float4 av = make_float4(0.f, 0.f, 0.f, 0.f);
        if (m_a < M) av = *(const float4*)(A + (size_t)m_a * lda + k0 + a_k);
        As[a_k + 0][a_row] = av.x;
        As[a_k + 1][a_row] = av.y;
        As[a_k + 2][a_row] = av.z;
        As[a_k + 3][a_row] = av.w;
        float4 bv = *(const float4*)(B + (size_t)(k0 + b_row) * ldb + bn + b_c);
        *(float4*)&Bs[b_row][b_c] = bv;
        __syncthreads();
#pragma unroll
        for (int kk = 0; kk < 16; kk++) {
            float4 a = *(const float4*)&As[kk][tr * 4];
            float4 b = *(const float4*)&Bs[kk][tc * 4];
            acc[0][0] += a.x * b.x; acc[0][1] += a.x * b.y; acc[0][2] += a.x * b.z; acc[0][3] += a.x * b.w;
            acc[1][0] += a.y * b.x; acc[1][1] += a.y * b.y; acc[1][2] += a.y * b.z; acc[1][3] += a.y * b.w;
            acc[2][0] += a.z * b.x; acc[2][1] += a.z * b.y; acc[2][2] += a.z * b.z; acc[2][3] += a.z * b.w;
            acc[3][0] += a.w * b.x; acc[3][1] += a.w * b.y; acc[3][2] += a.w * b.z; acc[3][3] += a.w * b.w;
        }
        __syncthreads();
    }

    float bb[4] = {0.f, 0.f, 0.f, 0.f};
    if (bias) {
#pragma unroll
        for (int j = 0; j < 4; j++) bb[j] = bias[bn + tc * 4 + j];
    }
#pragma unroll
    for (int i = 0; i < 4; i++) {
        int m = bm + tr * 4 + i;
        if (m < M) {
#pragma unroll
            for (int j = 0; j < 4; j++)
                C[(size_t)m * ldc + bn + tc * 4 + j] = acc[i][j] + bb[j];
        }
    }
}

// ---------------- TN GEMM with split-K atomics: C[M,N] += A^T B ----------------
// A is [K, M]-ish access: element (k, m) = A[k*lda + m]. B: (k, n) = B[k*ldb + n].
__global__ void sgemm_tn_atomic(const float* __restrict__ A, int lda,
                                const float* __restrict__ B, int ldb,
                                float* __restrict__ C, int ldc,
                                int M, int N, int K, int KC) {
    __shared__ __align__(16) float As[16][64];
    __shared__ __align__(16) float Bs[16][64];
    int tid = threadIdx.x;
    int bm = blockIdx.y * 64, bn = blockIdx.x * 64;
    int k_begin = blockIdx.z * KC;
    int k_end = min(k_begin + KC, K);
    int tr = tid >> 4, tc = tid & 15;
    int l_row = tid >> 4;        // 0..15
    int l_c = (tid & 15) * 4;    // 0..60

    float acc[4][4] = {};

    for (int k0 = k_begin; k0 < k_end; k0 += 16) {
        int row = k0 + l_row;
        float4 av = make_float4(0.f, 0.f, 0.f, 0.f);
        float4 bv = make_float4(0.f, 0.f, 0.f, 0.f);
        if (row < k_end) {
            av = *(const float4*)(A + (size_t)row * lda + bm + l_c);
            bv = *(const float4*)(B + (size_t)row * ldb + bn + l_c);
        }
        *(float4*)&As[l_row][l_c] = av;
        *(float4*)&Bs[l_row][l_c] = bv;
        __syncthreads();
#pragma unroll
        for (int kk = 0; kk < 16; kk++) {
            float4 a = *(const float4*)&As[kk][tr * 4];
            float4 b = *(const float4*)&Bs[kk][tc * 4];
            acc[0][0] += a.x * b.x; acc[0][1] += a.x * b.y; acc[0][2] += a.x * b.z; acc[0][3] += a.x * b.w;
            acc[1][0] += a.y * b.x; acc[1][1] += a.y * b.y; acc[1][2] += a.y * b.z; acc[1][3] += a.y * b.w;
            acc[2][0] += a.z * b.x; acc[2][1] += a.z * b.y; acc[2][2] += a.z * b.z; acc[2][3] += a.z * b.w;
            acc[3][0] += a.w * b.x; acc[3][1] += a.w * b.y; acc[3][2] += a.w * b.z; acc[3][3] += a.w * b.w;
        }
        __syncthreads();
    }

#pragma unroll
    for (int i = 0; i < 4; i++) {
        int m = bm + tr * 4 + i;
        if (m < M) {
#pragma unroll
            for (int j = 0; j < 4; j++)
                atomicAdd(&C[(size_t)m * ldc + bn + tc * 4 + j], acc[i][j]);
        }
    }
}

// ---------------- LayerNorm + ReLU (row-wise over 128) ----------------
__global__ void ln_relu_kernel(const float* __restrict__ in, const float* __restrict__ g,
                               const float* __restrict__ b, float* __restrict__ out) {
    __shared__ float sh[4];
    int tid = threadIdx.x;
    for (int n = blockIdx.x; n < NN; n += gridDim.x) {
        float v = in[(size_t)n * HH + tid];
        float mu = blockReduce128(v, sh) * (1.0f / 128.0f);
        float d = v - mu;
        float var = blockReduce128(d * d, sh) * (1.0f / 128.0f);
        float o = d * rsqrtf(var + LN_EPS) * g[tid] + b[tid];
        out[(size_t)n * HH + tid] = fmaxf(o, 0.0f);
    }
}

// ---------------- BatchNorm(eval) + ReLU, elementwise ----------------
__global__ void bn_relu_kernel(const float* __restrict__ in, const float* __restrict__ g,
                               const float* __restrict__ b, float* __restrict__ out) {
    const float s = rsqrtf(1.0f + LN_EPS);
    size_t total = (size_t)NN * HH;
    size_t i = (size_t)blockIdx.x * blockDim.x + threadIdx.x;
    size_t stride = (size_t)gridDim.x * blockDim.x;
    for (; i < total; i += stride) {
        int c = (int)(i & (HH - 1));
        out[i] = fmaxf(in[i] * s * g[c] + b[c], 0.0f);
    }
}

// ---------------- Q/K reductions: sum q^2, sum k^2, column sums of k ----------------
__global__ void reduce_qk_kernel(const float* __restrict__ q, const float* __restrict__ k,
                                 float* __restrict__ red, float* __restrict__ ksum) {
    __shared__ float sh[256];
    int tid = threadIdx.x;  // blockDim = 256
    size_t total = (size_t)NN * HH2;
    size_t stride = (size_t)gridDim.x * blockDim.x;  // multiple of 256
    float sq = 0.f, sk = 0.f, kc = 0.f;
    for (size_t i = (size_t)blockIdx.x * 256 + tid; i < total; i += stride) {
        float qv = q[i], kv = k[i];
        sq += qv * qv;
        sk += kv * kv;
        kc += kv;  // column index of i is always == tid (stride multiple of 256)
    }
    atomicAdd(&ksum[tid], kc);
    sh[tid] = sq;
    __syncthreads();
    for (int o = 128; o > 0; o >>= 1) {
        if (tid < o) sh[tid] += sh[tid + o];
        __syncthreads();
    }
    if (tid == 0) atomicAdd(&red[0], sh[0]);
    __syncthreads();
    sh[tid] = sk;
    __syncthreads();
    for (int o = 128; o > 0; o >>= 1) {
        if (tid < o) sh[tid] += sh[tid + o];
        __syncthreads();
    }
    if (tid == 0) atomicAdd(&red[1], sh[0]);
}

// ---------------- attention finalize: num/norm, mean heads, residual, LN, ReLU ----------------
__global__ void attn_finalize_kernel(const float* __restrict__ num, const float* __restrict__ q,
                                     const float* __restrict__ v, const float* __restrict__ ht,
                                     const float* __restrict__ ksum, const float* __restrict__ red,
                                     const float* __restrict__ g, const float* __restrict__ b,
                                     float* __restrict__ x1) {
    __shared__ float ks_s[HH2];
    __shared__ float sh[4];
    int tid = threadIdx.x;  // 128
    ks_s[tid] = ksum[tid];
    ks_s[HH + tid] = ksum[HH + tid];
    float inv = rsqrtf(red[0]) * rsqrtf(red[1]);  // 1/(||q||*||k||)
    __syncthreads();
    for (int n = blockIdx.x; n < NN; n += gridDim.x) {
        size_t b2 = (size_t)n * HH2;
        float q0 = q[b2 + tid], q1 = q[b2 + HH + tid];
        float s0 = blockReduce128(q0 * ks_s[tid], sh);
        float s1 = blockReduce128(q1 * ks_s[HH + tid], sh);
        float nrm0 = inv * s0 + NFf;
        float nrm1 = inv * s1 + NFf;
        float num0 = inv * num[b2 + tid] + NFf * v[b2 + tid];
        float num1 = inv * num[b2 + HH + tid] + NFf * v[b2 + HH + tid];
        float attn = 0.5f * (num0 / nrm0 + num1 / nrm1);
        float xv = 0.5f * (attn + ht[(size_t)n * HH + tid]);
        float mu = blockReduce128(xv, sh) * (1.0f / 128.0f);
        float d = xv - mu;
        float var = blockReduce128(d * d, sh) * (1.0f / 128.0f);
        float o = d * rsqrtf(var + LN_EPS) * g[tid] + b[tid];
        x1[(size_t)n * HH + tid] = fmaxf(o, 0.0f);
    }
}

// ---------------- graph: degree, edge values, scatter ----------------
__global__ void deg_kernel(const int* __restrict__ ei, float* __restrict__ deg) {
    int i = blockIdx.x * blockDim.x + threadIdx.x;
    int stride = gridDim.x * blockDim.x;
    for (int e = i; e < EE; e += stride) atomicAdd(&deg[ei[EE + e]], 1.0f);
}

__global__ void val_kernel(const int* __restrict__ ei, const float* __restrict__ deg,
                           float* __restrict__ val) {
    int i = blockIdx.x * blockDim.x + threadIdx.x;
    int stride = gridDim.x * blockDim.x;
    for (int e = i; e < EE; e += stride) {
        float dr = deg[ei[e]];
        float dc = deg[ei[EE + e]];
        val[e] = (dr > 0.0f && dc > 0.0f) ? rsqrtf(dr * dc) : 0.0f;
    }
}

// one warp per edge; lane handles 4 channels
__global__ void scatter_kernel(const int* __restrict__ ei, const float* __restrict__ val,
                               const float* __restrict__ hg, float* __restrict__ agg) {
    int lane = threadIdx.x & 31;
    int w = (blockIdx.x * blockDim.x + threadIdx.x) >> 5;
    int nw = (gridDim.x * blockDim.x) >> 5;
    for (int e = w; e < EE; e += nw) {
        float vv = val[e];
        if (vv == 0.0f) continue;
        int r = ei[e], c = ei[EE + e];
        float4 h = *(const float4*)(hg + (size_t)r * HH + lane * 4);
        float* dst = agg + (size_t)c * HH + lane * 4;
        atomicAdd(dst + 0, vv * h.x);
        atomicAdd(dst + 1, vv * h.y);
        atomicAdd(dst + 2, vv * h.z);
        atomicAdd(dst + 3, vv * h.w);
    }
}

// ---------------- BN1 + ReLU + residual + mix: y = GW*(relu(bn(h2))+hg) + (1-GW)*x1 ----------------
__global__ void combine_kernel(const float* __restrict__ h2, const float* __restrict__ hg,
                               const float* __restrict__ x1, const float* __restrict__ g,
                               const float* __restrict__ b, float* __restrict__ y) {
    const float s = rsqrtf(1.0f + LN_EPS);
    size_t total = (size_t)NN * HH;
    size_t i = (size_t)blockIdx.x * blockDim.x + threadIdx.x;
    size_t stride = (size_t)gridDim.x * blockDim.x;
    for (; i < total; i += stride) {
        int c = (int)(i & (HH - 1));
        float x2 = fmaxf(h2[i] * s * g[c] + b[c], 0.0f) + hg[i];
        y[i] = GW * x2 + (1.0f - GW) * x1[i];
    }
}

// ---------------- host launcher ----------------
static void launch_sgemm(const float* A, int lda, const float* B, int ldb,
                         const float* bias, float* C, int ldc, int M, int N, int K) {
    dim3 grid((N + 63) / 64, (M + 63) / 64, 1);
    sgemm_kernel<<<grid, 256>>>(A, lda, B, ldb, bias, C, ldc, M, N, K);
}

extern "C" void kernel_launch(void* const* d_in, const int* in_sizes, int n_in,
                              void* d_out, int out_size) {
    const float* x = (const float*)d_in[0];
    const int* ei = (const int*)d_in[1];
    const float* t_fc_w = (const float*)d_in[2];
    const float* t_fc_b = (const float*)d_in[3];
    const float* t_ln0_g = (const float*)d_in[4];
    const float* t_ln0_b = (const float*)d_in[5];
    const float* t_wq_w = (const float*)d_in[6];
    const float* t_wq_b = (const float*)d_in[7];
    const float* t_wk_w = (const float*)d_in[8];
    const float* t_wk_b = (const float*)d_in[9];
    const float* t_wv_w = (const float*)d_in[10];
    const float* t_wv_b = (const float*)d_in[11];
    const float* t_ln1_g = (const float*)d_in[12];
    const float* t_ln1_b = (const float*)d_in[13];
    const float* g_fc_w = (const float*)d_in[14];
    const float* g_fc_b = (const float*)d_in[15];
    const float* g_bn0_g = (const float*)d_in[16];
    const float* g_bn0_b = (const float*)d_in[17];
    const float* g_conv_w = (const float*)d_in[18];
    const float* g_conv_b = (const float*)d_in[19];
    const float* g_bn1_g = (const float*)d_in[20];
    const float* g_bn1_b = (const float*)d_in[21];
    const float* fc_w = (const float*)d_in[22];
    const float* fc_b = (const float*)d_in[23];
    float* out = (float*)d_out;

    float *p_scratch, *p_ht, *p_hg, *p_q, *p_k, *p_v, *p_x1, *p_agg, *p_y;
    float *p_deg, *p_val, *p_kvs, *p_red, *p_ksum;
    cudaGetSymbolAddress((void**)&p_scratch, g_scratch);
    cudaGetSymbolAddress((void**)&p_ht, g_ht);
    cudaGetSymbolAddress((void**)&p_hg, g_hg);
    cudaGetSymbolAddress((void**)&p_q, g_q);
    cudaGetSymbolAddress((void**)&p_k, g_k);
    cudaGetSymbolAddress((void**)&p_v, g_v);
    cudaGetSymbolAddress((void**)&p_x1, g_x1);
    cudaGetSymbolAddress((void**)&p_agg, g_agg);
    cudaGetSymbolAddress((void**)&p_y, g_y);
    cudaGetSymbolAddress((void**)&p_deg, g_deg);
    cudaGetSymbolAddress((void**)&p_val, g_val);
    cudaGetSymbolAddress((void**)&p_kvs, g_kvs);
    cudaGetSymbolAddress((void**)&p_red, g_red);
    cudaGetSymbolAddress((void**)&p_ksum, g_ksum);

    // ---- Trans branch ----
    // pre_t = x @ t_fc_w + b
    launch_sgemm(x, FF, t_fc_w, HH, t_fc_b, p_scratch, HH, NN, HH, FF);
    ln_relu_kernel<<<4096, 128>>>(p_scratch, t_ln0_g, t_ln0_b, p_ht);

    // q,k,v = ht @ W + b  [N,256]
    launch_sgemm(p_ht, HH, t_wq_w, HH2, t_wq_b, p_q, HH2, NN, HH2, HH);
    launch_sgemm(p_ht, HH, t_wk_w, HH2, t_wk_b, p_k, HH2, NN, HH2, HH);
    launch_sgemm(p_ht, HH, t_wv_w, HH2, t_wv_b, p_v, HH2, NN, HH2, HH);

    zero_kernel<<<1, 256>>>(p_red, 2);
    zero_kernel<<<1, 256>>>(p_ksum, HH2);
    zero_kernel<<<64, 256>>>(p_kvs, 2 * HH * HH);
    reduce_qk_kernel<<<512, 256>>>(p_q, p_k, p_red, p_ksum);

    // kvs_h = K_h^T V_h (split-K atomic)
    const int KC = 784;
    const int SPLITS = (NN + KC - 1) / KC;
    for (int h = 0; h < 2; h++) {
        dim3 grid(2, 2, SPLITS);
        sgemm_tn_atomic<<<grid, 256>>>(p_k + h * HH, HH2, p_v + h * HH, HH2,
                                       p_kvs + h * HH * HH, HH, HH, HH, NN, KC);
    }

    // num_h = Q_h @ kvs_h
    for (int h = 0; h < 2; h++) {
        launch_sgemm(p_q + h * HH, HH2, p_kvs + h * HH * HH, HH, nullptr,
                     p_scratch + h * HH, HH2, NN, HH, HH);
    }

    attn_finalize_kernel<<<4096, 128>>>(p_scratch, p_q, p_v, p_ht, p_ksum, p_red,
                                        t_ln1_g, t_ln1_b, p_x1);

    // ---- Graph branch ----
    launch_sgemm(x, FF, g_fc_w, HH, g_fc_b, p_scratch, HH, NN, HH, FF);
    bn_relu_kernel<<<4096, 256>>>(p_scratch, g_bn0_g, g_bn0_b, p_hg);

    zero_kernel<<<256, 256>>>(p_deg, NN);
    deg_kernel<<<2048, 256>>>(ei, p_deg);
    val_kernel<<<2048, 256>>>(ei, p_deg, p_val);
    zero_kernel<<<4096, 256>>>(p_agg, (size_t)NN * HH);
    scatter_kernel<<<4096, 256>>>(ei, p_val, p_hg, p_agg);

    // h2 = agg @ conv_w + b
    launch_sgemm(p_agg, HH, g_conv_w, HH, g_conv_b, p_scratch, HH, NN, HH, HH);
    combine_kernel<<<4096, 256>>>(p_scratch, p_hg, p_x1, g_bn1_g, g_bn1_b, p_y);

    // out = y @ fc_w + fc_b
    launch_sgemm(p_y, HH, fc_w, CC, fc_b, out, CC, NN, CC, HH);
}

// round 2
// speedup vs baseline: 1.5560x; 1.5560x over previous
#include <cuda_runtime.h>
#include <cuda_bf16.h>
#include <mma.h>
#include <math.h>

using namespace nvcuda;

// Problem constants
#define NN 100000
#define FF 512
#define HH 128
#define HH2 256
#define EE 1600000
#define CC 64
#define NFf 100000.0f
#define LN_EPS 1e-5f
#define GW 0.8f

// ---------------- scratch (device globals; allocation-free) ----------------
__device__ float g_scratch[(size_t)NN * HH2];  // pre-activations, then attn "num"
__device__ float g_ht[(size_t)NN * HH];
__device__ float g_hg[(size_t)NN * HH];
__device__ float g_q[(size_t)NN * HH2];
__device__ float g_k[(size_t)NN * HH2];
__device__ float g_v[(size_t)NN * HH2];
__device__ float g_x1[(size_t)NN * HH];
__device__ float g_agg[(size_t)NN * HH];
__device__ float g_y[(size_t)NN * HH];
__device__ float g_deg[NN];
__device__ float g_val[EE];
__device__ float g_kvs[2 * HH * HH];
__device__ float g_red[2];     // sum q^2, sum k^2
__device__ float g_ksum[HH2];  // column sums of k

// ---------------- utility ----------------
__global__ void zero_kernel(float* p, size_t n) {
    size_t i = (size_t)blockIdx.x * blockDim.x + threadIdx.x;
    size_t stride = (size_t)gridDim.x * blockDim.x;
    for (; i < n; i += stride) p[i] = 0.0f;
}

__device__ __forceinline__ float blockReduce128(float v, volatile float* sh) {
    unsigned m = 0xffffffffu;
    v += __shfl_down_sync(m, v, 16);
    v += __shfl_down_sync(m, v, 8);
    v += __shfl_down_sync(m, v, 4);
    v += __shfl_down_sync(m, v, 2);
    v += __shfl_down_sync(m, v, 1);
    int lane = threadIdx.x & 31, warp = threadIdx.x >> 5;
    if (lane == 0) sh[warp] = v;
    __syncthreads();
    float r = sh[0] + sh[1] + sh[2] + sh[3];
    __syncthreads();
    return r;
}

__device__ __forceinline__ float f2tf(float x) {
    float r;
    asm("cvt.rna.tf32.f32 %0, %1;" : "=f"(r) : "f"(x));
    return r;
}
__device__ __forceinline__ float4 f2tf4(float4 v) {
    v.x = f2tf(v.x); v.y = f2tf(v.y); v.z = f2tf(v.z); v.w = f2tf(v.w);
    return v;
}
__device__ __forceinline__ void red_add_v4(float* p, float4 v) {
    asm volatile("red.global.add.v4.f32 [%0], {%1,%2,%3,%4};"
                 :: "l"(p), "f"(v.x), "f"(v.y), "f"(v.z), "f"(v.w) : "memory");
}

// ============ TF32 tensor-core GEMM: C[M,N] = A[M,K]@B[K,N] (+bias) ============
// BM=64, BN=128, BK=32, 256 threads (8 warps, 2x4 warp grid, warp tile 32x32).
// Double-buffered shared tiles, register prefetch. K%32==0 required (holds for all calls).
#define GEMM_SMEM (( (2*64*36) + (2*32*132) ) * 4)   // 52224 bytes

__global__ void __launch_bounds__(256) gemm_tf32_kernel(
    const float* __restrict__ A, int lda,
    const float* __restrict__ B, int ldb,
    const float* __restrict__ bias,
    float* __restrict__ C, int ldc,
    int M, int N, int K) {
    extern __shared__ float sm[];
    float* As = sm;                 // [2][64][36]
    float* Bs = sm + 2 * 64 * 36;   // [2][32][132]

    const int tid = threadIdx.x;
    const int wid = tid >> 5;
    const int wr = wid >> 2;  // 0..1  (32-row slab)
    const int wc = wid & 3;   // 0..3  (32-col slab)
    const int bm = blockIdx.y * 64;
    const int bn = blockIdx.x * 128;

    wmma::fragment<wmma::accumulator, 16, 16, 8, float> acc[2][2];
#pragma unroll
    for (int i = 0; i < 2; i++)
#pragma unroll
        for (int j = 0; j < 2; j++) wmma::fill_fragment(acc[i][j], 0.0f);

    const int arow = tid >> 3, acol = (tid & 7) * 4;
    const int brow = tid >> 5, bcol = (tid & 31) * 4;
    const bool aval0 = (bm + arow) < M;
    const bool aval1 = (bm + arow + 32) < M;
    const bool bvalc = (bn + bcol) < N;
    const float4 z4 = make_float4(0.f, 0.f, 0.f, 0.f);

    const float* Ap0 = A + (size_t)(bm + arow) * lda + acol;
    const float* Ap1 = A + (size_t)(bm + arow + 32) * lda + acol;
    const float* Bp = B + (size_t)brow * ldb + bn + bcol;

    // prologue: tile 0
    {
        float4 a0 = aval0 ? *(const float4*)(Ap0) : z4;
        float4 a1 = aval1 ? *(const float4*)(Ap1) : z4;
        *(float4*)(As + arow * 36 + acol) = f2tf4(a0);
        *(float4*)(As + (arow + 32) * 36 + acol) = f2tf4(a1);
#pragma unroll
        for (int j = 0; j < 4; j++) {
            float4 b = bvalc ? *(const float4*)(Bp + (size_t)(j * 8) * ldb) : z4;
            *(float4*)(Bs + (brow + j * 8) * 132 + bcol) = f2tf4(b);
        }
    }
    __syncthreads();

    const int T = K >> 5;
    for (int t = 0; t < T; t++) {
        int s = t & 1;
        float4 a0n, a1n, bn4[4];
        bool has = (t + 1) < T;
        if (has) {
            int k0 = (t + 1) << 5;
            a0n = aval0 ? *(const float4*)(Ap0 + k0) : z4;
            a1n = aval1 ? *(const float4*)(Ap1 + k0) : z4;
#pragma unroll
            for (int j = 0; j < 4; j++)
                bn4[j] = bvalc ? *(const float4*)(Bp + (size_t)(k0 + j * 8) * ldb) : z4;
        }
#pragma unroll
        for (int ks = 0; ks < 4; ks++) {
            wmma::fragment<wmma::matrix_a, 16, 16, 8, wmma::precision::tf32, wmma::row_major> af[2];
            wmma::load_matrix_sync(af[0], As + s * 2304 + (wr * 32) * 36 + ks * 8, 36);
            wmma::load_matrix_sync(af[1], As + s * 2304 + (wr * 32 + 16) * 36 + ks * 8, 36);
#pragma unroll
            for (int nc = 0; nc < 2; nc++) {
                wmma::fragment<wmma::matrix_b, 16, 16, 8, wmma::precision::tf32, wmma::row_major> bf;
                wmma::load_matrix_sync(bf, Bs + s * 4224 + (ks * 8) * 132 + wc * 32 + nc * 16, 132);
                wmma::mma_sync(acc[0][nc], af[0], bf, acc[0][nc]);
                wmma::mma_sync(acc[1][nc], af[1], bf, acc[1][nc]);
            }
        }
        if (has) {
            int s2 = s ^ 1;
            *(float4*)(As + s2 * 2304 + arow * 36 + acol) = f2tf4(a0n);
            *(float4*)(As + s2 * 2304 + (arow + 32) * 36 + acol) = f2tf4(a1n);
#pragma unroll
            for (int j = 0; j < 4; j++)
                *(float4*)(Bs + s2 * 4224 + (brow + j * 8) * 132 + bcol) = f2tf4(bn4[j]);
        }
        __syncthreads();
    }

    // epilogue: stage via shared, then guarded vectorized store + bias
    float* stg = sm;  // 64*128 floats = 32KB, fits
#pragma unroll
    for (int mi = 0; mi < 2; mi++)
#pragma unroll
        for (int nc = 0; nc < 2; nc++)
            wmma::store_matrix_sync(stg + (wr * 32 + mi * 16) * 128 + wc * 32 + nc * 16,
                                    acc[mi][nc], 128, wmma::mem_row_major);
    __syncthreads();

    int oc = (tid & 31) * 4;
    int orb = tid >> 5;
    bool cok = (bn + oc) < N;
    float4 bb = z4;
    if (bias && cok) bb = *(const float4*)(bias + bn + oc);
#pragma unroll
    for (int j = 0; j < 8; j++) {
        int r = orb + j * 8;
        int m = bm + r;
        if (m < M && cok) {
            float4 v = *(float4*)(stg + r * 128 + oc);
            v.x += bb.x; v.y += bb.y; v.z += bb.z; v.w += bb.w;
            *(float4*)(C + (size_t)m * ldc + bn + oc) = v;
        }
    }
}

// ============ TF32 split-K kvs: C[128,128] += K_h^T @ V_h over K=100000 ============
// grid (SPLITS, 2 heads). Single-buffered tiles (small kernel), red.v4 epilogue.
#define KVS_SMEM (128 * 128 * 4)  // 65536 (staging dominates; tiles = 33792 fit inside)

__global__ void __launch_bounds__(256) kvs_tf32_kernel(
    const float* __restrict__ Km, const float* __restrict__ Vm,
    float* __restrict__ Ckvs, int KC) {
    extern __shared__ float sm[];
    float* Ks = sm;             // [32][132]
    float* Vs = sm + 32 * 132;  // [32][132]

    const int tid = threadIdx.x;
    const int wid = tid >> 5;
    const int wr = wid >> 1;  // 0..3 (32-row slab of output)
    const int wc = wid & 1;   // 0..1 (64-col slab)
    const int head = blockIdx.y;
    const float* Kp = Km + head * HH;
    const float* Vp = Vm + head * HH;
    float* Cp = Ckvs + head * HH * HH;
    const int kb = blockIdx.x * KC;
    const int ke = min(kb + KC, NN);
    const float4 z4 = make_float4(0.f, 0.f, 0.f, 0.f);

    wmma::fragment<wmma::accumulator, 16, 16, 8, float> acc[2][4];
#pragma unroll
    for (int i = 0; i < 2; i++)
#pragma unroll
        for (int j = 0; j < 4; j++) wmma::fill_fragment(acc[i][j], 0.0f);

    const int lrow = tid >> 5, lcol = (tid & 31) * 4;

    for (int t = kb; t < ke; t += 32) {
#pragma unroll
        for (int j = 0; j < 4; j++) {
            int kr = t + lrow + j * 8;
            float4 kv = z4, vv = z4;
            if (kr < ke) {
                kv = *(const float4*)(Kp + (size_t)kr * HH2 + lcol);
                vv = *(const float4*)(Vp + (size_t)kr * HH2 + lcol);
            }
            *(float4*)(Ks + (lrow + j * 8) * 132 + lcol) = f2tf4(kv);
            *(float4*)(Vs + (lrow + j * 8) * 132 + lcol) = f2tf4(vv);
        }
        __syncthreads();
#pragma unroll
        for (int ks = 0; ks < 4; ks++) {
            wmma::fragment<wmma::matrix_a, 16, 16, 8, wmma::precision::tf32, wmma::col_major> af[2];
            wmma::load_matrix_sync(af[0], Ks + (ks * 8) * 132 + wr * 32, 132);
            wmma::load_matrix_sync(af[1], Ks + (ks * 8) * 132 + wr * 32 + 16, 132);
#pragma unroll
            for (int ni = 0; ni < 4; ni++) {
                wmma::fragment<wmma::matrix_b, 16, 16, 8, wmma::precision::tf32, wmma::row_major> bf;
                wmma::load_matrix_sync(bf, Vs + (ks * 8) * 132 + wc * 64 + ni * 16, 132);
                wmma::mma_sync(acc[0][ni], af[0], bf, acc[0][ni]);
                wmma::mma_sync(acc[1][ni], af[1], bf, acc[1][ni]);
            }
        }
        __syncthreads();
    }

    float* stg = sm;  // 128x128
#pragma unroll
    for (int mi = 0; mi < 2; mi++)
#pragma unroll
        for (int ni = 0; ni < 4; ni++)
            wmma::store_matrix_sync(stg + (wr * 32 + mi * 16) * 128 + wc * 64 + ni * 16,
                                    acc[mi][ni], 128, wmma::mem_row_major);
    __syncthreads();

    int oc = (tid & 31) * 4;
    int orr = tid >> 5;
#pragma unroll
    for (int j = 0; j < 16; j++) {
        int r = orr + j * 8;
        float4 v = *(float4*)(stg + r * 128 + oc);
        red_add_v4(Cp + r * 128 + oc, v);
    }
}

// ---------------- LayerNorm + ReLU (row-wise over 128) ----------------
__global__ void ln_relu_kernel(const float* __restrict__ in, const float* __restrict__ g,
                               const float* __restrict__ b, float* __restrict__ out) {
    __shared__ float sh[4];
    int tid = threadIdx.x;
    for (int n = blockIdx.x; n < NN; n += gridDim.x) {
        float v = in[(size_t)n * HH + tid];
        float mu = blockReduce128(v, sh) * (1.0f / 128.0f);
        float d = v - mu;
        float var = blockReduce128(d * d, sh) * (1.0f / 128.0f);
        float o = d * rsqrtf(var + LN_EPS) * g[tid] + b[tid];
        out[(size_t)n * HH + tid] = fmaxf(o, 0.0f);
    }
}

// ---------------- BatchNorm(eval) + ReLU, elementwise ----------------
__global__ void bn_relu_kernel(const float* __restrict__ in, const float* __restrict__ g,
                               const float* __restrict__ b, float* __restrict__ out) {
    const float s = rsqrtf(1.0f + LN_EPS);
    size_t total = (size_t)NN * HH;
    size_t i = (size_t)blockIdx.x * blockDim.x + threadIdx.x;
    size_t stride = (size_t)gridDim.x * blockDim.x;
    for (; i < total; i += stride) {
        int c = (int)(i & (HH - 1));
        out[i] = fmaxf(in[i] * s * g[c] + b[c], 0.0f);
    }
}

// ---------------- Q/K reductions ----------------
__global__ void reduce_qk_kernel(const float* __restrict__ q, const float* __restrict__ k,
                                 float* __restrict__ red, float* __restrict__ ksum) {
    __shared__ float sh[256];
    int tid = threadIdx.x;  // blockDim = 256
    size_t total = (size_t)NN * HH2;
    size_t stride = (size_t)gridDim.x * blockDim.x;
    float sq = 0.f, sk = 0.f, kc = 0.f;
    for (size_t i = (size_t)blockIdx.x * 256 + tid; i < total; i += stride) {
        float qv = q[i], kv = k[i];
        sq += qv * qv;
        sk += kv * kv;
        kc += kv;
    }
    atomicAdd(&ksum[tid], kc);
    sh[tid] = sq;
    __syncthreads();
    for (int o = 128; o > 0; o >>= 1) {
        if (tid < o) sh[tid] += sh[tid + o];
        __syncthreads();
    }
    if (tid == 0) atomicAdd(&red[0], sh[0]);
    __syncthreads();
    sh[tid] = sk;
    __syncthreads();
    for (int o = 128; o > 0; o >>= 1) {
        if (tid < o) sh[tid] += sh[tid + o];
        __syncthreads();
    }
    if (tid == 0) atomicAdd(&red[1], sh[0]);
}

// ---------------- attention finalize ----------------
__global__ void attn_finalize_kernel(const float* __restrict__ num, const float* __restrict__ q,
                                     const float* __restrict__ v, const float* __restrict__ ht,
                                     const float* __restrict__ ksum, const float* __restrict__ red,
                                     const float* __restrict__ g, const float* __restrict__ b,
                                     float* __restrict__ x1) {
    __shared__ float ks_s[HH2];
    __shared__ float sh[4];
    int tid = threadIdx.x;  // 128
    ks_s[tid] = ksum[tid];
    ks_s[HH + tid] = ksum[HH + tid];
    float inv = rsqrtf(red[0]) * rsqrtf(red[1]);  // 1/(||q||*||k||)
    __syncthreads();
    for (int n = blockIdx.x; n < NN; n += gridDim.x) {
        size_t b2 = (size_t)n * HH2;
        float q0 = q[b2 + tid], q1 = q[b2 + HH + tid];
        float s0 = blockReduce128(q0 * ks_s[tid], sh);
        float s1 = blockReduce128(q1 * ks_s[HH + tid], sh);
        float nrm0 = inv * s0 + NFf;
        float nrm1 = inv * s1 + NFf;
        float num0 = inv * num[b2 + tid] + NFf * v[b2 + tid];
        float num1 = inv * num[b2 + HH + tid] + NFf * v[b2 + HH + tid];
        float attn = 0.5f * (num0 / nrm0 + num1 / nrm1);
        float xv = 0.5f * (attn + ht[(size_t)n * HH + tid]);
        float mu = blockReduce128(xv, sh) * (1.0f / 128.0f);
        float d = xv - mu;
        float var = blockReduce128(d * d, sh) * (1.0f / 128.0f);
        float o = d * rsqrtf(var + LN_EPS) * g[tid] + b[tid];
        x1[(size_t)n * HH + tid] = fmaxf(o, 0.0f);
    }
}

// ---------------- graph: degree, edge values, scatter ----------------
__global__ void deg_kernel(const int* __restrict__ ei, float* __restrict__ deg) {
    int i = blockIdx.x * blockDim.x + threadIdx.x;
    int stride = gridDim.x * blockDim.x;
    for (int e = i; e < EE; e += stride) atomicAdd(&deg[ei[EE + e]], 1.0f);
}

__global__ void val_kernel(const int* __restrict__ ei, const float* __restrict__ deg,
                           float* __restrict__ val) {
    int i = blockIdx.x * blockDim.x + threadIdx.x;
    int stride = gridDim.x * blockDim.x;
    for (int e = i; e < EE; e += stride) {
        float dr = deg[ei[e]];
        float dc = deg[ei[EE + e]];
        val[e] = (dr > 0.0f && dc > 0.0f) ? rsqrtf(dr * dc) : 0.0f;
    }
}

// one warp per edge; lane handles 4 channels; vectorized global reduction
__global__ void scatter_kernel(const int* __restrict__ ei, const float* __restrict__ val,
                               const float* __restrict__ hg, float* __restrict__ agg) {
    int lane = threadIdx.x & 31;
    int w = (blockIdx.x * blockDim.x + threadIdx.x) >> 5;
    int nw = (gridDim.x * blockDim.x) >> 5;
    for (int e = w; e < EE; e += nw) {
        float vv = val[e];
        if (vv == 0.0f) continue;
        int r = ei[e], c = ei[EE + e];
        float4 h = *(const float4*)(hg + (size_t)r * HH + lane * 4);
        float4 o = make_float4(vv * h.x, vv * h.y, vv * h.z, vv * h.w);
        red_add_v4(agg + (size_t)c * HH + lane * 4, o);
    }
}

// ---------------- BN1 + ReLU + residual + mix ----------------
__global__ void combine_kernel(const float* __restrict__ h2, const float* __restrict__ hg,
                               const float* __restrict__ x1, const float* __restrict__ g,
                               const float* __restrict__ b, float* __restrict__ y) {
    const float s = rsqrtf(1.0f + LN_EPS);
    size_t total = (size_t)NN * HH;
    size_t i = (size_t)blockIdx.x * blockDim.x + threadIdx.x;
    size_t stride = (size_t)gridDim.x * blockDim.x;
    for (; i < total; i += stride) {
        int c = (int)(i & (HH - 1));
        float x2 = fmaxf(h2[i] * s * g[c] + b[c], 0.0f) + hg[i];
        y[i] = GW * x2 + (1.0f - GW) * x1[i];
    }
}

// ---------------- host launcher ----------------
static void launch_gemm(const float* A, int lda, const float* B, int ldb,
                        const float* bias, float* C, int ldc, int M, int N, int K) {
    dim3 grid((N + 127) / 128, (M + 63) / 64);
    gemm_tf32_kernel<<<grid, 256, GEMM_SMEM>>>(A, lda, B, ldb, bias, C, ldc, M, N, K);
}

extern "C" void kernel_launch(void* const* d_in, const int* in_sizes, int n_in,
                              void* d_out, int out_size) {
    const float* x = (const float*)d_in[0];
    const int* ei = (const int*)d_in[1];
    const float* t_fc_w = (const float*)d_in[2];
    const float* t_fc_b = (const float*)d_in[3];
    const float* t_ln0_g = (const float*)d_in[4];
    const float* t_ln0_b = (const float*)d_in[5];
    const float* t_wq_w = (const float*)d_in[6];
    const float* t_wq_b = (const float*)d_in[7];
    const float* t_wk_w = (const float*)d_in[8];
    const float* t_wk_b = (const float*)d_in[9];
    const float* t_wv_w = (const float*)d_in[10];
    const float* t_wv_b = (const float*)d_in[11];
    const float* t_ln1_g = (const float*)d_in[12];
    const float* t_ln1_b = (const float*)d_in[13];
    const float* g_fc_w = (const float*)d_in[14];
    const float* g_fc_b = (const float*)d_in[15];
    const float* g_bn0_g = (const float*)d_in[16];
    const float* g_bn0_b = (const float*)d_in[17];
    const float* g_conv_w = (const float*)d_in[18];
    const float* g_conv_b = (const float*)d_in[19];
    const float* g_bn1_g = (const float*)d_in[20];
    const float* g_bn1_b = (const float*)d_in[21];
    const float* fc_w = (const float*)d_in[22];
    const float* fc_b = (const float*)d_in[23];
    float* out = (float*)d_out;

    static bool attr_done = false;
    cudaFuncSetAttribute(gemm_tf32_kernel, cudaFuncAttributeMaxDynamicSharedMemorySize, GEMM_SMEM);
    cudaFuncSetAttribute(kvs_tf32_kernel, cudaFuncAttributeMaxDynamicSharedMemorySize, KVS_SMEM);
    (void)attr_done;

    float *p_scratch, *p_ht, *p_hg, *p_q, *p_k, *p_v, *p_x1, *p_agg, *p_y;
    float *p_deg, *p_val, *p_kvs, *p_red, *p_ksum;
    cudaGetSymbolAddress((void**)&p_scratch, g_scratch);
    cudaGetSymbolAddress((void**)&p_ht, g_ht);
    cudaGetSymbolAddress((void**)&p_hg, g_hg);
    cudaGetSymbolAddress((void**)&p_q, g_q);
    cudaGetSymbolAddress((void**)&p_k, g_k);
    cudaGetSymbolAddress((void**)&p_v, g_v);
    cudaGetSymbolAddress((void**)&p_x1, g_x1);
    cudaGetSymbolAddress((void**)&p_agg, g_agg);
    cudaGetSymbolAddress((void**)&p_y, g_y);
    cudaGetSymbolAddress((void**)&p_deg, g_deg);
    cudaGetSymbolAddress((void**)&p_val, g_val);
    cudaGetSymbolAddress((void**)&p_kvs, g_kvs);
    cudaGetSymbolAddress((void**)&p_red, g_red);
    cudaGetSymbolAddress((void**)&p_ksum, g_ksum);

    // ---- Trans branch ----
    launch_gemm(x, FF, t_fc_w, HH, t_fc_b, p_scratch, HH, NN, HH, FF);
    ln_relu_kernel<<<4096, 128>>>(p_scratch, t_ln0_g, t_ln0_b, p_ht);

    launch_gemm(p_ht, HH, t_wq_w, HH2, t_wq_b, p_q, HH2, NN, HH2, HH);
    launch_gemm(p_ht, HH, t_wk_w, HH2, t_wk_b, p_k, HH2, NN, HH2, HH);
    launch_gemm(p_ht, HH, t_wv_w, HH2, t_wv_b, p_v, HH2, NN, HH2, HH);

    zero_kernel<<<1, 256>>>(p_red, 2);
    zero_kernel<<<1, 256>>>(p_ksum, HH2);
    zero_kernel<<<64, 256>>>(p_kvs, 2 * HH * HH);
    reduce_qk_kernel<<<512, 256>>>(p_q, p_k, p_red, p_ksum);

    // kvs_h = K_h^T V_h (tf32 tensor split-K, red.v4 accumulate)
    {
        const int KC = 704;
        const int SPLITS = (NN + KC - 1) / KC;  // 143
        dim3 grid(SPLITS, 2);
        kvs_tf32_kernel<<<grid, 256, KVS_SMEM>>>(p_k, p_v, p_kvs, KC);
    }

    // num_h = Q_h @ kvs_h
    for (int h = 0; h < 2; h++) {
        launch_gemm(p_q + h * HH, HH2, p_kvs + h * HH * HH, HH, nullptr,
                    p_scratch + h * HH, HH2, NN, HH, HH);
    }

    attn_finalize_kernel<<<4096, 128>>>(p_scratch, p_q, p_v, p_ht, p_ksum, p_red,
                                        t_ln1_g, t_ln1_b, p_x1);

    // ---- Graph branch ----
    launch_gemm(x, FF, g_fc_w, HH, g_fc_b, p_scratch, HH, NN, HH, FF);
    bn_relu_kernel<<<4096, 256>>>(p_scratch, g_bn0_g, g_bn0_b, p_hg);

    zero_kernel<<<256, 256>>>(p_deg, NN);
    deg_kernel<<<2048, 256>>>(ei, p_deg);
    val_kernel<<<2048, 256>>>(ei, p_deg, p_val);
    zero_kernel<<<4096, 256>>>(p_agg, (size_t)NN * HH);
    scatter_kernel<<<4096, 256>>>(ei, p_val, p_hg, p_agg);

    launch_gemm(p_agg, HH, g_conv_w, HH, g_conv_b, p_scratch, HH, NN, HH, HH);
    combine_kernel<<<4096, 256>>>(p_scratch, p_hg, p_x1, g_bn1_g, g_bn1_b, p_y);

    launch_gemm(p_y, HH, fc_w, CC, fc_b, out, CC, NN, CC, HH);
}

// round 4
// speedup vs baseline: 1.7364x; 1.1159x over previous
#include <cuda_runtime.h>
#include <cuda_bf16.h>
#include <mma.h>
#include <math.h>

using namespace nvcuda;

// Problem constants
#define NN 100000
#define FF 512
#define HH 128
#define HH2 256
#define EE 1600000
#define CC 64
#define NFf 100000.0f
#define LN_EPS 1e-5f
#define GW 0.8f

// ---------------- scratch (device globals; allocation-free) ----------------
__device__ float g_scratch[(size_t)NN * HH2];  // pre-activations, then attn "num"
__device__ float g_ht[(size_t)NN * HH];
__device__ float g_hg[(size_t)NN * HH];
__device__ float g_q[(size_t)NN * HH2];
__device__ float g_k[(size_t)NN * HH2];
__device__ float g_v[(size_t)NN * HH2];
__device__ float g_x1[(size_t)NN * HH];
__device__ float g_agg[(size_t)NN * HH];
__device__ float g_y[(size_t)NN * HH];
__device__ float g_kvs[2 * HH * HH];
__device__ float g_red[2];     // sum q^2, sum k^2
__device__ float g_ksum[HH2];  // column sums of k
// CSR machinery
__device__ int g_cnt[NN];
__device__ int g_rowptr[NN + 1];
__device__ int g_cursor[NN];
__device__ int g_csr[EE];
__device__ float g_f[NN];
__device__ int g_bsum[128];

// ---------------- utility ----------------
__global__ void zero_kernel(float* p, size_t n) {
    size_t i = (size_t)blockIdx.x * blockDim.x + threadIdx.x;
    size_t stride = (size_t)gridDim.x * blockDim.x;
    for (; i < n; i += stride) p[i] = 0.0f;
}
__global__ void zero_int_kernel(int* p, size_t n) {
    size_t i = (size_t)blockIdx.x * blockDim.x + threadIdx.x;
    size_t stride = (size_t)gridDim.x * blockDim.x;
    for (; i < n; i += stride) p[i] = 0;
}

__device__ __forceinline__ float blockReduce128(float v, volatile float* sh) {
    unsigned m = 0xffffffffu;
    v += __shfl_down_sync(m, v, 16);
    v += __shfl_down_sync(m, v, 8);
    v += __shfl_down_sync(m, v, 4);
    v += __shfl_down_sync(m, v, 2);
    v += __shfl_down_sync(m, v, 1);
    int lane = threadIdx.x & 31, warp = threadIdx.x >> 5;
    if (lane == 0) sh[warp] = v;
    __syncthreads();
    float r = sh[0] + sh[1] + sh[2] + sh[3];
    __syncthreads();
    return r;
}

__device__ __forceinline__ float warpAllSum(float v) {
    unsigned m = 0xffffffffu;
    v += __shfl_xor_sync(m, v, 16);
    v += __shfl_xor_sync(m, v, 8);
    v += __shfl_xor_sync(m, v, 4);
    v += __shfl_xor_sync(m, v, 2);
    v += __shfl_xor_sync(m, v, 1);
    return v;
}

__device__ __forceinline__ float f2tf(float x) {
    float r;
    asm("cvt.rna.tf32.f32 %0, %1;" : "=f"(r) : "f"(x));
    return r;
}
__device__ __forceinline__ float4 f2tf4(float4 v) {
    v.x = f2tf(v.x); v.y = f2tf(v.y); v.z = f2tf(v.z); v.w = f2tf(v.w);
    return v;
}
__device__ __forceinline__ void red_add_v4(float* p, float4 v) {
    asm volatile("red.global.add.v4.f32 [%0], {%1,%2,%3,%4};"
                 :: "l"(p), "f"(v.x), "f"(v.y), "f"(v.z), "f"(v.w) : "memory");
}
__device__ __forceinline__ void cp16(float* smem, const float* gmem, bool pred) {
    unsigned saddr = (unsigned)__cvta_generic_to_shared(smem);
    int sz = pred ? 16 : 0;
    asm volatile("cp.async.cg.shared.global [%0], [%1], 16, %2;"
                 :: "r"(saddr), "l"(gmem), "r"(sz));
}

// ============ TF32 tensor GEMM v3: BM=128 BN=128 BK=32, cp.async 2-stage ============
#define BM 128
#define BN 128
#define BK 32
#define AS_LD 36
#define BS_LD 132
#define A_STAGE (BM * AS_LD)              // 4608 floats
#define B_STAGE (BK * BS_LD)              // 4224 floats
#define STAGE (A_STAGE + B_STAGE)         // 8832 floats
#define GEMM_SMEM (2 * STAGE * 4)         // 70656 bytes

#define EPI_NONE 0
#define EPI_LN 1
#define EPI_BN 2
#define EPI_CMB 3

template <int EPI>
__global__ void __launch_bounds__(256, 2) gemm_v3(
    const float* __restrict__ A, int lda,
    const float* __restrict__ B, int ldb,
    const float* __restrict__ bias,
    float* __restrict__ C, int ldc,
    int M, int N, int K,
    const float* __restrict__ eg, const float* __restrict__ eb,
    const float* __restrict__ hgp, const float* __restrict__ x1p) {
    extern __shared__ float sm[];
    const int tid = threadIdx.x;
    const int wid = tid >> 5;
    const int lane = tid & 31;
    const int wr = wid >> 1;  // 0..3 (32-row slab)
    const int wc = wid & 1;   // 0..1 (64-col slab)
    const int bm = blockIdx.y * BM;
    const int bn = blockIdx.x * BN;

    wmma::fragment<wmma::accumulator, 16, 16, 8, float> acc[2][4];
#pragma unroll
    for (int i = 0; i < 2; i++)
#pragma unroll
        for (int j = 0; j < 4; j++) wmma::fill_fragment(acc[i][j], 0.0f);

    const int T = K >> 5;

    // ---- async load of one K-tile into stage s ----
    auto load_stage = [&](int t, int s) {
        const int k0 = t << 5;
        float* sA = sm + s * STAGE;
        float* sB = sm + s * STAGE + A_STAGE;
#pragma unroll
        for (int j = 0; j < 4; j++) {
            int idx = tid + j * 256;        // 0..1023 over 128x8 float4
            int r = idx >> 3, c4 = idx & 7;
            bool ok = (bm + r) < M;
            const float* src = A + (size_t)(ok ? bm + r : 0) * lda + k0 + c4 * 4;
            cp16(sA + r * AS_LD + c4 * 4, src, ok);
        }
#pragma unroll
        for (int j = 0; j < 4; j++) {
            int idx = tid + j * 256;        // 32x32 float4
            int r = idx >> 5, c4 = idx & 31;
            bool ok = (bn + c4 * 4) < N;
            const float* src = B + (size_t)(k0 + r) * ldb + bn + (ok ? c4 * 4 : 0);
            cp16(sB + r * BS_LD + c4 * 4, src, ok);
        }
        asm volatile("cp.async.commit_group;");
    };

    load_stage(0, 0);

    for (int t = 0; t < T; t++) {
        const int s = t & 1;
        if (t + 1 < T) {
            load_stage(t + 1, s ^ 1);
            asm volatile("cp.async.wait_group 1;");
        } else {
            asm volatile("cp.async.wait_group 0;");
        }
        __syncthreads();
        const float* sA = sm + s * STAGE;
        const float* sB = sm + s * STAGE + A_STAGE;
#pragma unroll
        for (int ks = 0; ks < 4; ks++) {
            wmma::fragment<wmma::matrix_a, 16, 16, 8, wmma::precision::tf32, wmma::row_major> af[2];
#pragma unroll
            for (int mi = 0; mi < 2; mi++) {
                wmma::load_matrix_sync(af[mi], sA + (wr * 32 + mi * 16) * AS_LD + ks * 8, AS_LD);
#pragma unroll
                for (int e = 0; e < af[mi].num_elements; e++) af[mi].x[e] = f2tf(af[mi].x[e]);
            }
#pragma unroll
            for (int ni = 0; ni < 4; ni++) {
                wmma::fragment<wmma::matrix_b, 16, 16, 8, wmma::precision::tf32, wmma::row_major> bf;
                wmma::load_matrix_sync(bf, sB + (ks * 8) * BS_LD + wc * 64 + ni * 16, BS_LD);
#pragma unroll
                for (int e = 0; e < bf.num_elements; e++) bf.x[e] = f2tf(bf.x[e]);
                wmma::mma_sync(acc[0][ni], af[0], bf, acc[0][ni]);
                wmma::mma_sync(acc[1][ni], af[1], bf, acc[1][ni]);
            }
        }
        __syncthreads();
    }

    // ---- stage accumulators to shared ----
    float* stg = sm;  // 128x128 floats = 64KB <= 70656
#pragma unroll
    for (int mi = 0; mi < 2; mi++)
#pragma unroll
        for (int ni = 0; ni < 4; ni++)
            wmma::store_matrix_sync(stg + (wr * 32 + mi * 16) * 128 + wc * 64 + ni * 16,
                                    acc[mi][ni], 128, wmma::mem_row_major);
    __syncthreads();

    const float4 z4 = make_float4(0.f, 0.f, 0.f, 0.f);

    if (EPI == EPI_LN) {
        // row-parallel: warp wid handles rows wid*16 .. wid*16+15; lane owns 4 cols
        float4 bb = bias ? *(const float4*)(bias + lane * 4) : z4;
        float4 gg = *(const float4*)(eg + lane * 4);
        float4 be = *(const float4*)(eb + lane * 4);
#pragma unroll
        for (int i = 0; i < 16; i++) {
            int r = wid * 16 + i;
            int m = bm + r;
            float4 v = *(float4*)(stg + r * 128 + lane * 4);
            v.x += bb.x; v.y += bb.y; v.z += bb.z; v.w += bb.w;
            float mu = warpAllSum(v.x + v.y + v.z + v.w) * (1.0f / 128.0f);
            float4 d = make_float4(v.x - mu, v.y - mu, v.z - mu, v.w - mu);
            float var = warpAllSum(d.x * d.x + d.y * d.y + d.z * d.z + d.w * d.w) * (1.0f / 128.0f);
            float rs = rsqrtf(var + LN_EPS);
            float4 o;
            o.x = fmaxf(d.x * rs * gg.x + be.x, 0.f);
            o.y = fmaxf(d.y * rs * gg.y + be.y, 0.f);
            o.z = fmaxf(d.z * rs * gg.z + be.z, 0.f);
            o.w = fmaxf(d.w * rs * gg.w + be.w, 0.f);
            if (m < M) *(float4*)(C + (size_t)m * ldc + lane * 4) = o;
        }
    } else {
        int c4 = (tid & 31) * 4;
        int r0 = tid >> 5;
        bool cok = (bn + c4) < N;
        float4 bb = (bias && cok) ? *(const float4*)(bias + bn + c4) : z4;
        float4 gg = z4, be = z4;
        const float sbn = rsqrtf(1.0f + LN_EPS);
        if (EPI == EPI_BN || EPI == EPI_CMB) {
            if (cok) {
                gg = *(const float4*)(eg + bn + c4);
                be = *(const float4*)(eb + bn + c4);
                gg.x *= sbn; gg.y *= sbn; gg.z *= sbn; gg.w *= sbn;
            }
        }
#pragma unroll
        for (int j = 0; j < 16; j++) {
            int r = r0 + j * 8;
            int m = bm + r;
            if (m < M && cok) {
                float4 v = *(float4*)(stg + r * 128 + c4);
                v.x += bb.x; v.y += bb.y; v.z += bb.z; v.w += bb.w;
                if (EPI == EPI_BN || EPI == EPI_CMB) {
                    v.x = fmaxf(v.x * gg.x + be.x, 0.f);
                    v.y = fmaxf(v.y * gg.y + be.y, 0.f);
                    v.z = fmaxf(v.z * gg.z + be.z, 0.f);
                    v.w = fmaxf(v.w * gg.w + be.w, 0.f);
                }
                if (EPI == EPI_CMB) {
                    float4 h = *(const float4*)(hgp + (size_t)m * HH + c4);
                    float4 x1v = *(const float4*)(x1p + (size_t)m * HH + c4);
                    v.x = GW * (v.x + h.x) + (1.0f - GW) * x1v.x;
                    v.y = GW * (v.y + h.y) + (1.0f - GW) * x1v.y;
                    v.z = GW * (v.z + h.z) + (1.0f - GW) * x1v.z;
                    v.w = GW * (v.w + h.w) + (1.0f - GW) * x1v.w;
                }
                *(float4*)(C + (size_t)m * ldc + bn + c4) = v;
            }
        }
    }
}

// ============ TF32 split-K kvs: C[128,128] += K_h^T @ V_h ============
#define KVS_SMEM (128 * 128 * 4)

__global__ void __launch_bounds__(256) kvs_tf32_kernel(
    const float* __restrict__ Km, const float* __restrict__ Vm,
    float* __restrict__ Ckvs, int KC) {
    extern __shared__ float sm[];
    float* Ks = sm;             // [32][132]
    float* Vs = sm + 32 * 132;  // [32][132]

    const int tid = threadIdx.x;
    const int wid = tid >> 5;
    const int wr = wid >> 1;
    const int wc = wid & 1;
    const int head = blockIdx.y;
    const float* Kp = Km + head * HH;
    const float* Vp = Vm + head * HH;
    float* Cp = Ckvs + head * HH * HH;
    const int kb = blockIdx.x * KC;
    const int ke = min(kb + KC, NN);
    const float4 z4 = make_float4(0.f, 0.f, 0.f, 0.f);

    wmma::fragment<wmma::accumulator, 16, 16, 8, float> acc[2][4];
#pragma unroll
    for (int i = 0; i < 2; i++)
#pragma unroll
        for (int j = 0; j < 4; j++) wmma::fill_fragment(acc[i][j], 0.0f);

    const int lrow = tid >> 5, lcol = (tid & 31) * 4;

    for (int t = kb; t < ke; t += 32) {
#pragma unroll
        for (int j = 0; j < 4; j++) {
            int kr = t + lrow + j * 8;
            float4 kv = z4, vv = z4;
            if (kr < ke) {
                kv = *(const float4*)(Kp + (size_t)kr * HH2 + lcol);
                vv = *(const float4*)(Vp + (size_t)kr * HH2 + lcol);
            }
            *(float4*)(Ks + (lrow + j * 8) * 132 + lcol) = f2tf4(kv);
            *(float4*)(Vs + (lrow + j * 8) * 132 + lcol) = f2tf4(vv);
        }
        __syncthreads();
#pragma unroll
        for (int ks = 0; ks < 4; ks++) {
            wmma::fragment<wmma::matrix_a, 16, 16, 8, wmma::precision::tf32, wmma::col_major> af[2];
            wmma::load_matrix_sync(af[0], Ks + (ks * 8) * 132 + wr * 32, 132);
            wmma::load_matrix_sync(af[1], Ks + (ks * 8) * 132 + wr * 32 + 16, 132);
#pragma unroll
            for (int ni = 0; ni < 4; ni++) {
                wmma::fragment<wmma::matrix_b, 16, 16, 8, wmma::precision::tf32, wmma::row_major> bf;
                wmma::load_matrix_sync(bf, Vs + (ks * 8) * 132 + wc * 64 + ni * 16, 132);
                wmma::mma_sync(acc[0][ni], af[0], bf, acc[0][ni]);
                wmma::mma_sync(acc[1][ni], af[1], bf, acc[1][ni]);
            }
        }
        __syncthreads();
    }

    float* stg = sm;
#pragma unroll
    for (int mi = 0; mi < 2; mi++)
#pragma unroll
        for (int ni = 0; ni < 4; ni++)
            wmma::store_matrix_sync(stg + (wr * 32 + mi * 16) * 128 + wc * 64 + ni * 16,
                                    acc[mi][ni], 128, wmma::mem_row_major);
    __syncthreads();

    int oc = (tid & 31) * 4;
    int orr = tid >> 5;
#pragma unroll
    for (int j = 0; j < 16; j++) {
        int r = orr + j * 8;
        float4 v = *(float4*)(stg + r * 128 + oc);
        red_add_v4(Cp + r * 128 + oc, v);
    }
}

// ---------------- Q/K reductions ----------------
__global__ void reduce_qk_kernel(const float* __restrict__ q, const float* __restrict__ k,
                                 float* __restrict__ red, float* __restrict__ ksum) {
    __shared__ float sh[256];
    int tid = threadIdx.x;  // blockDim = 256
    size_t total = (size_t)NN * HH2;
    size_t stride = (size_t)gridDim.x * blockDim.x;
    float sq = 0.f, sk = 0.f, kc = 0.f;
    for (size_t i = (size_t)blockIdx.x * 256 + tid; i < total; i += stride) {
        float qv = q[i], kv = k[i];
        sq += qv * qv;
        sk += kv * kv;
        kc += kv;
    }
    atomicAdd(&ksum[tid], kc);
    sh[tid] = sq;
    __syncthreads();
    for (int o = 128; o > 0; o >>= 1) {
        if (tid < o) sh[tid] += sh[tid + o];
        __syncthreads();
    }
    if (tid == 0) atomicAdd(&red[0], sh[0]);
    __syncthreads();
    sh[tid] = sk;
    __syncthreads();
    for (int o = 128; o > 0; o >>= 1) {
        if (tid < o) sh[tid] += sh[tid + o];
        __syncthreads();
    }
    if (tid == 0) atomicAdd(&red[1], sh[0]);
}

// ---------------- attention finalize ----------------
__global__ void attn_finalize_kernel(const float* __restrict__ num, const float* __restrict__ q,
                                     const float* __restrict__ v, const float* __restrict__ ht,
                                     const float* __restrict__ ksum, const float* __restrict__ red,
                                     const float* __restrict__ g, const float* __restrict__ b,
                                     float* __restrict__ x1) {
    __shared__ float ks_s[HH2];
    __shared__ float sh[4];
    int tid = threadIdx.x;  // 128
    ks_s[tid] = ksum[tid];
    ks_s[HH + tid] = ksum[HH + tid];
    float inv = rsqrtf(red[0]) * rsqrtf(red[1]);
    __syncthreads();
    for (int n = blockIdx.x; n < NN; n += gridDim.x) {
        size_t b2 = (size_t)n * HH2;
        float q0 = q[b2 + tid], q1 = q[b2 + HH + tid];
        float s0 = blockReduce128(q0 * ks_s[tid], sh);
        float s1 = blockReduce128(q1 * ks_s[HH + tid], sh);
        float nrm0 = inv * s0 + NFf;
        float nrm1 = inv * s1 + NFf;
        float num0 = inv * num[b2 + tid] + NFf * v[b2 + tid];
        float num1 = inv * num[b2 + HH + tid] + NFf * v[b2 + HH + tid];
        float attn = 0.5f * (num0 / nrm0 + num1 / nrm1);
        float xv = 0.5f * (attn + ht[(size_t)n * HH + tid]);
        float mu = blockReduce128(xv, sh) * (1.0f / 128.0f);
        float d = xv - mu;
        float var = blockReduce128(d * d, sh) * (1.0f / 128.0f);
        float o = d * rsqrtf(var + LN_EPS) * g[tid] + b[tid];
        x1[(size_t)n * HH + tid] = fmaxf(o, 0.0f);
    }
}

// ---------------- CSR build + gather ----------------
__global__ void deg_int_kernel(const int* __restrict__ ei, int* __restrict__ cnt) {
    int i = blockIdx.x * blockDim.x + threadIdx.x;
    int stride = gridDim.x * blockDim.x;
    for (int e = i; e < EE; e += stride) atomicAdd(&cnt[ei[EE + e]], 1);
}

__global__ void f_kernel(const int* __restrict__ cnt, float* __restrict__ f) {
    int i = blockIdx.x * blockDim.x + threadIdx.x;
    int stride = gridDim.x * blockDim.x;
    for (int n = i; n < NN; n += stride)
        f[n] = (cnt[n] > 0) ? rsqrtf((float)cnt[n]) : 0.0f;
}

#define SCAN_NB 98   // ceil(100000/1024)
__global__ void scan_partial(const int* __restrict__ cnt, int* __restrict__ bsum) {
    __shared__ int sh[32];
    int tid = threadIdx.x;  // 1024
    int i = blockIdx.x * 1024 + tid;
    int v = (i < NN) ? cnt[i] : 0;
    unsigned m = 0xffffffffu;
    int s = v;
    s += __shfl_down_sync(m, s, 16);
    s += __shfl_down_sync(m, s, 8);
    s += __shfl_down_sync(m, s, 4);
    s += __shfl_down_sync(m, s, 2);
    s += __shfl_down_sync(m, s, 1);
    if ((tid & 31) == 0) sh[tid >> 5] = s;
    __syncthreads();
    if (tid < 32) {
        int t = sh[tid];
        t += __shfl_down_sync(m, t, 16);
        t += __shfl_down_sync(m, t, 8);
        t += __shfl_down_sync(m, t, 4);
        t += __shfl_down_sync(m, t, 2);
        t += __shfl_down_sync(m, t, 1);
        if (tid == 0) bsum[blockIdx.x] = t;
    }
}

__global__ void scan_bsum(int* __restrict__ bsum) {
    __shared__ int sh[128];
    int tid = threadIdx.x;  // 128
    int v = (tid < SCAN_NB) ? bsum[tid] : 0;
    sh[tid] = v;
    __syncthreads();
    for (int off = 1; off < 128; off <<= 1) {
        int t = (tid >= off) ? sh[tid - off] : 0;
        __syncthreads();
        sh[tid] += t;
        __syncthreads();
    }
    if (tid < SCAN_NB) bsum[tid] = sh[tid] - v;  // exclusive
}

__global__ void scan_final(const int* __restrict__ cnt, const int* __restrict__ bsum,
                           int* __restrict__ rowptr, int* __restrict__ cursor) {
    __shared__ int sh[1024];
    int tid = threadIdx.x;  // 1024
    int i = blockIdx.x * 1024 + tid;
    int v = (i < NN) ? cnt[i] : 0;
    sh[tid] = v;
    __syncthreads();
    for (int off = 1; off < 1024; off <<= 1) {
        int t = (tid >= off) ? sh[tid - off] : 0;
        __syncthreads();
        sh[tid] += t;
        __syncthreads();
    }
    int ex = sh[tid] - v + bsum[blockIdx.x];
    if (i < NN) {
        rowptr[i] = ex;
        cursor[i] = ex;
    }
    if (i == NN - 1) rowptr[NN] = EE;
}

__global__ void fill_csr(const int* __restrict__ ei, int* __restrict__ cursor,
                         int* __restrict__ csr) {
    int i = blockIdx.x * blockDim.x + threadIdx.x;
    int stride = gridDim.x * blockDim.x;
    for (int e = i; e < EE; e += stride) {
        int c = ei[EE + e];
        int pos = atomicAdd(&cursor[c], 1);
        csr[pos] = ei[e];
    }
}

// one warp per node; lane owns 4 channels
__global__ void gather_kernel(const int* __restrict__ rowptr, const int* __restrict__ csr,
                              const float* __restrict__ f, const float* __restrict__ hg,
                              float* __restrict__ agg) {
    int lane = threadIdx.x & 31;
    int w = (blockIdx.x * blockDim.x + threadIdx.x) >> 5;
    if (w >= NN) return;
    int n = w;
    int s = rowptr[n], e = rowptr[n + 1];
    float4 acc = make_float4(0.f, 0.f, 0.f, 0.f);
    for (int j = s; j < e; j++) {
        int r = csr[j];
        float fr = f[r];
        float4 h = *(const float4*)(hg + (size_t)r * HH + lane * 4);
        acc.x += fr * h.x; acc.y += fr * h.y; acc.z += fr * h.z; acc.w += fr * h.w;
    }
    float fc = f[n];
    acc.x *= fc; acc.y *= fc; acc.z *= fc; acc.w *= fc;
    *(float4*)(agg + (size_t)n * HH + lane * 4) = acc;
}

// ---------------- host launcher ----------------
template <int EPI>
static void launch_gemm(const float* A, int lda, const float* B, int ldb,
                        const float* bias, float* C, int ldc, int M, int N, int K,
                        const float* eg = nullptr, const float* eb = nullptr,
                        const float* hg = nullptr, const float* x1 = nullptr) {
    dim3 grid((N + BN - 1) / BN, (M + BM - 1) / BM);
    gemm_v3<EPI><<<grid, 256, GEMM_SMEM>>>(A, lda, B, ldb, bias, C, ldc, M, N, K,
                                           eg, eb, hg, x1);
}

extern "C" void kernel_launch(void* const* d_in, const int* in_sizes, int n_in,
                              void* d_out, int out_size) {
    const float* x = (const float*)d_in[0];
    const int* ei = (const int*)d_in[1];
    const float* t_fc_w = (const float*)d_in[2];
    const float* t_fc_b = (const float*)d_in[3];
    const float* t_ln0_g = (const float*)d_in[4];
    const float* t_ln0_b = (const float*)d_in[5];
    const float* t_wq_w = (const float*)d_in[6];
    const float* t_wq_b = (const float*)d_in[7];
    const float* t_wk_w = (const float*)d_in[8];
    const float* t_wk_b = (const float*)d_in[9];
    const float* t_wv_w = (const float*)d_in[10];
    const float* t_wv_b = (const float*)d_in[11];
    const float* t_ln1_g = (const float*)d_in[12];
    const float* t_ln1_b = (const float*)d_in[13];
    const float* g_fc_w = (const float*)d_in[14];
    const float* g_fc_b = (const float*)d_in[15];
    const float* g_bn0_g = (const float*)d_in[16];
    const float* g_bn0_b = (const float*)d_in[17];
    const float* g_conv_w = (const float*)d_in[18];
    const float* g_conv_b = (const float*)d_in[19];
    const float* g_bn1_g = (const float*)d_in[20];
    const float* g_bn1_b = (const float*)d_in[21];
    const float* fc_w = (const float*)d_in[22];
    const float* fc_b = (const float*)d_in[23];
    float* out = (float*)d_out;

    cudaFuncSetAttribute(gemm_v3<EPI_NONE>, cudaFuncAttributeMaxDynamicSharedMemorySize, GEMM_SMEM);
    cudaFuncSetAttribute(gemm_v3<EPI_LN>, cudaFuncAttributeMaxDynamicSharedMemorySize, GEMM_SMEM);
    cudaFuncSetAttribute(gemm_v3<EPI_BN>, cudaFuncAttributeMaxDynamicSharedMemorySize, GEMM_SMEM);
    cudaFuncSetAttribute(gemm_v3<EPI_CMB>, cudaFuncAttributeMaxDynamicSharedMemorySize, GEMM_SMEM);
    cudaFuncSetAttribute(kvs_tf32_kernel, cudaFuncAttributeMaxDynamicSharedMemorySize, KVS_SMEM);

    float *p_scratch, *p_ht, *p_hg, *p_q, *p_k, *p_v, *p_x1, *p_agg, *p_y;
    float *p_kvs, *p_red, *p_ksum, *p_f;
    int *p_cnt, *p_rowptr, *p_cursor, *p_csr, *p_bsum;
    cudaGetSymbolAddress((void**)&p_scratch, g_scratch);
    cudaGetSymbolAddress((void**)&p_ht, g_ht);
    cudaGetSymbolAddress((void**)&p_hg, g_hg);
    cudaGetSymbolAddress((void**)&p_q, g_q);
    cudaGetSymbolAddress((void**)&p_k, g_k);
    cudaGetSymbolAddress((void**)&p_v, g_v);
    cudaGetSymbolAddress((void**)&p_x1, g_x1);
    cudaGetSymbolAddress((void**)&p_agg, g_agg);
    cudaGetSymbolAddress((void**)&p_y, g_y);
    cudaGetSymbolAddress((void**)&p_kvs, g_kvs);
    cudaGetSymbolAddress((void**)&p_red, g_red);
    cudaGetSymbolAddress((void**)&p_ksum, g_ksum);
    cudaGetSymbolAddress((void**)&p_f, g_f);
    cudaGetSymbolAddress((void**)&p_cnt, g_cnt);
    cudaGetSymbolAddress((void**)&p_rowptr, g_rowptr);
    cudaGetSymbolAddress((void**)&p_cursor, g_cursor);
    cudaGetSymbolAddress((void**)&p_csr, g_csr);
    cudaGetSymbolAddress((void**)&p_bsum, g_bsum);

    // ---- Trans branch ----
    // ht = relu(LN(x @ t_fc_w + b))   (fused epilogue)
    launch_gemm<EPI_LN>(x, FF, t_fc_w, HH, t_fc_b, p_ht, HH, NN, HH, FF,
                        t_ln0_g, t_ln0_b);

    launch_gemm<EPI_NONE>(p_ht, HH, t_wq_w, HH2, t_wq_b, p_q, HH2, NN, HH2, HH);
    launch_gemm<EPI_NONE>(p_ht, HH, t_wk_w, HH2, t_wk_b, p_k, HH2, NN, HH2, HH);
    launch_gemm<EPI_NONE>(p_ht, HH, t_wv_w, HH2, t_wv_b, p_v, HH2, NN, HH2, HH);

    zero_kernel<<<1, 256>>>(p_red, 2);
    zero_kernel<<<1, 256>>>(p_ksum, HH2);
    zero_kernel<<<64, 256>>>(p_kvs, 2 * HH * HH);
    reduce_qk_kernel<<<512, 256>>>(p_q, p_k, p_red, p_ksum);

    {
        const int KC = 704;
        const int SPLITS = (NN + KC - 1) / KC;
        dim3 grid(SPLITS, 2);
        kvs_tf32_kernel<<<grid, 256, KVS_SMEM>>>(p_k, p_v, p_kvs, KC);
    }

    for (int h = 0; h < 2; h++) {
        launch_gemm<EPI_NONE>(p_q + h * HH, HH2, p_kvs + h * HH * HH, HH, nullptr,
                              p_scratch + h * HH, HH2, NN, HH, HH);
    }

    attn_finalize_kernel<<<4096, 128>>>(p_scratch, p_q, p_v, p_ht, p_ksum, p_red,
                                        t_ln1_g, t_ln1_b, p_x1);

    // ---- Graph branch ----
    // hg = relu(BN(x @ g_fc_w + b))   (fused epilogue)
    launch_gemm<EPI_BN>(x, FF, g_fc_w, HH, g_fc_b, p_hg, HH, NN, HH, FF,
                        g_bn0_g, g_bn0_b);

    zero_int_kernel<<<128, 256>>>(p_cnt, NN);
    deg_int_kernel<<<2048, 256>>>(ei, p_cnt);
    f_kernel<<<128, 256>>>(p_cnt, p_f);
    scan_partial<<<SCAN_NB, 1024>>>(p_cnt, p_bsum);
    scan_bsum<<<1, 128>>>(p_bsum);
    scan_final<<<SCAN_NB, 1024>>>(p_cnt, p_bsum, p_rowptr, p_cursor);
    fill_csr<<<2048, 256>>>(ei, p_cursor, p_csr);
    gather_kernel<<<(NN * 32 + 255) / 256, 256>>>(p_rowptr, p_csr, p_f, p_hg, p_agg);

    // y = GW*(relu(BN(agg @ conv_w + b)) + hg) + (1-GW)*x1   (fused epilogue)
    launch_gemm<EPI_CMB>(p_agg, HH, g_conv_w, HH, g_conv_b, p_y, HH, NN, HH, HH,
                         g_bn1_g, g_bn1_b, p_hg, p_x1);

    // out = y @ fc_w + fc_b
    launch_gemm<EPI_NONE>(p_y, HH, fc_w, CC, fc_b, out, CC, NN, CC, HH);
}

// round 6
// speedup vs baseline: 1.8074x; 1.0409x over previous
#include <cuda_runtime.h>
#include <cuda_bf16.h>
#include <mma.h>
#include <math.h>

using namespace nvcuda;

// Problem constants
#define NN 100000
#define FF 512
#define HH 128
#define HH2 256
#define EE 1600000
#define CC 64
#define NFf 100000.0f
#define LN_EPS 1e-5f
#define GW 0.8f

// ---------------- scratch (device globals; allocation-free) ----------------
__device__ float g_scratch[(size_t)NN * HH2];  // attn "num"
__device__ float g_ht[(size_t)NN * HH];
__device__ float g_hg[(size_t)NN * HH];
__device__ float g_q[(size_t)NN * HH2];
__device__ float g_k[(size_t)NN * HH2];
__device__ float g_v[(size_t)NN * HH2];
__device__ float g_x1[(size_t)NN * HH];
__device__ float g_agg[(size_t)NN * HH];
__device__ float g_y[(size_t)NN * HH];
__device__ float g_kvs[2 * HH * HH];
__device__ float g_red[2];     // sum q^2, sum k^2
__device__ float g_ksum[HH2];  // column sums of k
// pre-rounded (tf32) weights
#define WOFF_T 0
#define WOFF_G 65536
#define WOFF_Q 131072
#define WOFF_K 163840
#define WOFF_V 196608
#define WOFF_CONV 229376
#define WOFF_FC 245760
__device__ float g_wbuf[253952];
// CSR machinery
__device__ int g_cnt[NN];
__device__ int g_rowptr[NN + 1];
__device__ int g_cursor[NN];
__device__ int g_csr[EE];
__device__ float g_f[NN];
__device__ int g_bsum[128];

// ---------------- utility ----------------
__global__ void zero_kernel(float* p, size_t n) {
    size_t i = (size_t)blockIdx.x * blockDim.x + threadIdx.x;
    size_t stride = (size_t)gridDim.x * blockDim.x;
    for (; i < n; i += stride) p[i] = 0.0f;
}
__global__ void zero_int_kernel(int* p, size_t n) {
    size_t i = (size_t)blockIdx.x * blockDim.x + threadIdx.x;
    size_t stride = (size_t)gridDim.x * blockDim.x;
    for (; i < n; i += stride) p[i] = 0;
}

__device__ __forceinline__ float blockReduce128(float v, volatile float* sh) {
    unsigned m = 0xffffffffu;
    v += __shfl_down_sync(m, v, 16);
    v += __shfl_down_sync(m, v, 8);
    v += __shfl_down_sync(m, v, 4);
    v += __shfl_down_sync(m, v, 2);
    v += __shfl_down_sync(m, v, 1);
    int lane = threadIdx.x & 31, warp = threadIdx.x >> 5;
    if (lane == 0) sh[warp] = v;
    __syncthreads();
    float r = sh[0] + sh[1] + sh[2] + sh[3];
    __syncthreads();
    return r;
}

__device__ __forceinline__ float warpAllSum(float v) {
    unsigned m = 0xffffffffu;
    v += __shfl_xor_sync(m, v, 16);
    v += __shfl_xor_sync(m, v, 8);
    v += __shfl_xor_sync(m, v, 4);
    v += __shfl_xor_sync(m, v, 2);
    v += __shfl_xor_sync(m, v, 1);
    return v;
}

__device__ __forceinline__ float f2tf(float x) {
    float r;
    asm("cvt.rna.tf32.f32 %0, %1;" : "=f"(r) : "f"(x));
    return r;
}
__device__ __forceinline__ float4 f2tf4(float4 v) {
    v.x = f2tf(v.x); v.y = f2tf(v.y); v.z = f2tf(v.z); v.w = f2tf(v.w);
    return v;
}
__device__ __forceinline__ void red_add_v4(float* p, float4 v) {
    asm volatile("red.global.add.v4.f32 [%0], {%1,%2,%3,%4};"
                 :: "l"(p), "f"(v.x), "f"(v.y), "f"(v.z), "f"(v.w) : "memory");
}
__device__ __forceinline__ void cp16(float* smem, const float* gmem, bool pred) {
    unsigned saddr = (unsigned)__cvta_generic_to_shared(smem);
    int sz = pred ? 16 : 0;
    asm volatile("cp.async.cg.shared.global [%0], [%1], 16, %2;"
                 :: "r"(saddr), "l"(gmem), "r"(sz));
}

// weight pre-rounding: copy with tf32 round into g_wbuf segments
__global__ void round_weights_kernel(const float* __restrict__ wt, const float* __restrict__ wg,
                                     const float* __restrict__ wq, const float* __restrict__ wk,
                                     const float* __restrict__ wv, const float* __restrict__ wc,
                                     const float* __restrict__ wf, float* __restrict__ dst) {
    int i = blockIdx.x * blockDim.x + threadIdx.x;
    int stride = gridDim.x * blockDim.x;
    for (int j = i; j < 253952; j += stride) {
        float v;
        if (j < WOFF_G) v = wt[j - WOFF_T];
        else if (j < WOFF_Q) v = wg[j - WOFF_G];
        else if (j < WOFF_K) v = wq[j - WOFF_Q];
        else if (j < WOFF_V) v = wk[j - WOFF_K];
        else if (j < WOFF_CONV) v = wv[j - WOFF_V];
        else if (j < WOFF_FC) v = wc[j - WOFF_CONV];
        else v = wf[j - WOFF_FC];
        dst[j] = f2tf(v);
    }
}

__global__ void round_inplace_kernel(float* p, int n) {
    int i = blockIdx.x * blockDim.x + threadIdx.x;
    int stride = gridDim.x * blockDim.x;
    for (int j = i; j < n; j += stride) p[j] = f2tf(p[j]);
}

// ============ TF32 tensor GEMM core: BM=64 BN=128 BK=32, cp.async 2-stage ============
// 256 threads, 8 warps in 2x4 grid, warp tile 32x32 (acc 2x2 frags).
// Result tile left staged in sm[0 .. 64*128) after return (synced).
#define BM 64
#define BN 128
#define BK 32
#define AS_LD 36
#define BS_LD 132
#define A_STAGE (BM * AS_LD)              // 2304 floats
#define B_STAGE (BK * BS_LD)              // 4224 floats
#define STAGE (A_STAGE + B_STAGE)         // 6528 floats
#define GEMM_SMEM (2 * STAGE * 4)         // 52224 bytes

template <bool CVTA>
__device__ __forceinline__ void gemm_core(
    const float* __restrict__ A, int lda, int M, int bm,
    const float* __restrict__ B, int ldb, int N, int bn,
    int K, float* sm) {
    const int tid = threadIdx.x;
    const int wid = tid >> 5;
    const int wr = wid >> 2;  // 0..1
    const int wc = wid & 3;   // 0..3

    wmma::fragment<wmma::accumulator, 16, 16, 8, float> acc[2][2];
#pragma unroll
    for (int i = 0; i < 2; i++)
#pragma unroll
        for (int j = 0; j < 2; j++) wmma::fill_fragment(acc[i][j], 0.0f);

    const int T = K >> 5;

    auto load_stage = [&](int t, int s) {
        const int k0 = t << 5;
        float* sA = sm + s * STAGE;
        float* sB = sm + s * STAGE + A_STAGE;
#pragma unroll
        for (int j = 0; j < 2; j++) {
            int idx = tid + j * 256;        // 64x8 float4
            int r = idx >> 3, c4 = idx & 7;
            bool ok = (bm + r) < M;
            const float* src = A + (size_t)(ok ? bm + r : 0) * lda + k0 + c4 * 4;
            cp16(sA + r * AS_LD + c4 * 4, src, ok);
        }
#pragma unroll
        for (int j = 0; j < 4; j++) {
            int idx = tid + j * 256;        // 32x32 float4
            int r = idx >> 5, c4 = idx & 31;
            bool ok = (bn + c4 * 4) < N;
            const float* src = B + (size_t)(k0 + r) * ldb + bn + (ok ? c4 * 4 : 0);
            cp16(sB + r * BS_LD + c4 * 4, src, ok);
        }
        asm volatile("cp.async.commit_group;");
    };

    load_stage(0, 0);

    for (int t = 0; t < T; t++) {
        const int s = t & 1;
        if (t + 1 < T) {
            load_stage(t + 1, s ^ 1);
            asm volatile("cp.async.wait_group 1;");
        } else {
            asm volatile("cp.async.wait_group 0;");
        }
        __syncthreads();
        const float* sA = sm + s * STAGE;
        const float* sB = sm + s * STAGE + A_STAGE;
#pragma unroll
        for (int ks = 0; ks < 4; ks++) {
            wmma::fragment<wmma::matrix_a, 16, 16, 8, wmma::precision::tf32, wmma::row_major> af[2];
#pragma unroll
            for (int mi = 0; mi < 2; mi++) {
                wmma::load_matrix_sync(af[mi], sA + (wr * 32 + mi * 16) * AS_LD + ks * 8, AS_LD);
                if (CVTA) {
#pragma unroll
                    for (int e = 0; e < af[mi].num_elements; e++) af[mi].x[e] = f2tf(af[mi].x[e]);
                }
            }
#pragma unroll
            for (int ni = 0; ni < 2; ni++) {
                wmma::fragment<wmma::matrix_b, 16, 16, 8, wmma::precision::tf32, wmma::row_major> bf;
                wmma::load_matrix_sync(bf, sB + (ks * 8) * BS_LD + wc * 32 + ni * 16, BS_LD);
                wmma::mma_sync(acc[0][ni], af[0], bf, acc[0][ni]);
                wmma::mma_sync(acc[1][ni], af[1], bf, acc[1][ni]);
            }
        }
        __syncthreads();
    }

    // stage result tile to sm[0 .. 8192)
#pragma unroll
    for (int mi = 0; mi < 2; mi++)
#pragma unroll
        for (int ni = 0; ni < 2; ni++)
            wmma::store_matrix_sync(sm + (wr * 32 + mi * 16) * 128 + wc * 32 + ni * 16,
                                    acc[mi][ni], 128, wmma::mem_row_major);
    __syncthreads();
}

// ---- fused x-GEMM: blockIdx.x==0 -> ht = relu(LN(x@Wt+bt)); ==1 -> hg = relu(BN(x@Wg+bg))
__global__ void __launch_bounds__(256, 3) gemm_fc_dual(
    const float* __restrict__ x, const float* __restrict__ wbuf,
    const float* __restrict__ bt, const float* __restrict__ ln_g, const float* __restrict__ ln_b,
    const float* __restrict__ bg, const float* __restrict__ bn_g, const float* __restrict__ bn_b,
    float* __restrict__ ht, float* __restrict__ hg) {
    extern __shared__ float sm[];
    const int which = blockIdx.x;
    const int bm = blockIdx.y * BM;
    const float* B = wbuf + (which ? WOFF_G : WOFF_T);
    gemm_core<true>(x, FF, NN, bm, B, HH, HH, 0, FF, sm);

    const int tid = threadIdx.x;
    const int wid = tid >> 5;
    const int lane = tid & 31;

    if (which == 0) {
        // LN + relu, row-parallel: warp handles 8 rows
        float4 bb = *(const float4*)(bt + lane * 4);
        float4 gg = *(const float4*)(ln_g + lane * 4);
        float4 be = *(const float4*)(ln_b + lane * 4);
#pragma unroll
        for (int i = 0; i < 8; i++) {
            int r = wid * 8 + i;
            int m = bm + r;
            float4 v = *(float4*)(sm + r * 128 + lane * 4);
            v.x += bb.x; v.y += bb.y; v.z += bb.z; v.w += bb.w;
            float mu = warpAllSum(v.x + v.y + v.z + v.w) * (1.0f / 128.0f);
            float4 d = make_float4(v.x - mu, v.y - mu, v.z - mu, v.w - mu);
            float var = warpAllSum(d.x * d.x + d.y * d.y + d.z * d.z + d.w * d.w) * (1.0f / 128.0f);
            float rs = rsqrtf(var + LN_EPS);
            float4 o;
            o.x = fmaxf(d.x * rs * gg.x + be.x, 0.f);
            o.y = fmaxf(d.y * rs * gg.y + be.y, 0.f);
            o.z = fmaxf(d.z * rs * gg.z + be.z, 0.f);
            o.w = fmaxf(d.w * rs * gg.w + be.w, 0.f);
            if (m < NN) *(float4*)(ht + (size_t)m * HH + lane * 4) = f2tf4(o);
        }
    } else {
        int c4 = lane * 4;
        int r0 = wid;
        const float sbn = rsqrtf(1.0f + LN_EPS);
        float4 bb = *(const float4*)(bg + c4);
        float4 gg = *(const float4*)(bn_g + c4);
        float4 be = *(const float4*)(bn_b + c4);
        gg.x *= sbn; gg.y *= sbn; gg.z *= sbn; gg.w *= sbn;
#pragma unroll
        for (int j = 0; j < 8; j++) {
            int r = r0 + j * 8;
            int m = bm + r;
            if (m < NN) {
                float4 v = *(float4*)(sm + r * 128 + c4);
                float4 o;
                o.x = fmaxf((v.x + bb.x) * gg.x + be.x, 0.f);
                o.y = fmaxf((v.y + bb.y) * gg.y + be.y, 0.f);
                o.z = fmaxf((v.z + bb.z) * gg.z + be.z, 0.f);
                o.w = fmaxf((v.w + bb.w) * gg.w + be.w, 0.f);
                *(float4*)(hg + (size_t)m * HH + c4) = f2tf4(o);
            }
        }
    }
}

// ---- fused QKV: grid.x = 6 (sel = x>>1 chooses q/k/v, half = x&1 chooses column group)
__global__ void __launch_bounds__(256, 3) gemm_qkv(
    const float* __restrict__ ht, const float* __restrict__ wbuf,
    const float* __restrict__ bq, const float* __restrict__ bk, const float* __restrict__ bv,
    float* __restrict__ q, float* __restrict__ k, float* __restrict__ v) {
    extern __shared__ float sm[];
    const int sel = blockIdx.x >> 1;
    const int bn = (blockIdx.x & 1) * 128;
    const int bm = blockIdx.y * BM;
    const float* B = wbuf + (sel == 0 ? WOFF_Q : (sel == 1 ? WOFF_K : WOFF_V));
    const float* bias = (sel == 0 ? bq : (sel == 1 ? bk : bv));
    float* C = (sel == 0 ? q : (sel == 1 ? k : v));
    gemm_core<false>(ht, HH, NN, bm, B, HH2, HH2, bn, HH, sm);

    const int tid = threadIdx.x;
    int c4 = (tid & 31) * 4;
    int r0 = tid >> 5;
    float4 bb = *(const float4*)(bias + bn + c4);
#pragma unroll
    for (int j = 0; j < 8; j++) {
        int r = r0 + j * 8;
        int m = bm + r;
        if (m < NN) {
            float4 o = *(float4*)(sm + r * 128 + c4);
            o.x += bb.x; o.y += bb.y; o.z += bb.z; o.w += bb.w;
            *(float4*)(C + (size_t)m * HH2 + bn + c4) = f2tf4(o);
        }
    }
}

// ---- num = Q_h @ kvs_h, both heads in one launch (grid.x = 2)
__global__ void __launch_bounds__(256, 3) gemm_num(
    const float* __restrict__ q, const float* __restrict__ kvs,
    float* __restrict__ num) {
    extern __shared__ float sm[];
    const int h = blockIdx.x;
    const int bm = blockIdx.y * BM;
    gemm_core<false>(q + h * HH, HH2, NN, bm, kvs + h * HH * HH, HH, HH, 0, HH, sm);

    const int tid = threadIdx.x;
    int c4 = (tid & 31) * 4;
    int r0 = tid >> 5;
#pragma unroll
    for (int j = 0; j < 8; j++) {
        int r = r0 + j * 8;
        int m = bm + r;
        if (m < NN)
            *(float4*)(num + (size_t)m * HH2 + h * HH + c4) = *(float4*)(sm + r * 128 + c4);
    }
}

// ---- conv GEMM + BN + relu + residual + mix epilogue -> y (rounded)
__global__ void __launch_bounds__(256, 3) gemm_conv_cmb(
    const float* __restrict__ agg, const float* __restrict__ wbuf,
    const float* __restrict__ bias, const float* __restrict__ bn_g, const float* __restrict__ bn_b,
    const float* __restrict__ hg, const float* __restrict__ x1,
    float* __restrict__ y) {
    extern __shared__ float sm[];
    const int bm = blockIdx.y * BM;
    gemm_core<false>(agg, HH, NN, bm, wbuf + WOFF_CONV, HH, HH, 0, HH, sm);

    const int tid = threadIdx.x;
    int c4 = (tid & 31) * 4;
    int r0 = tid >> 5;
    const float sbn = rsqrtf(1.0f + LN_EPS);
    float4 bb = *(const float4*)(bias + c4);
    float4 gg = *(const float4*)(bn_g + c4);
    float4 be = *(const float4*)(bn_b + c4);
    gg.x *= sbn; gg.y *= sbn; gg.z *= sbn; gg.w *= sbn;
#pragma unroll
    for (int j = 0; j < 8; j++) {
        int r = r0 + j * 8;
        int m = bm + r;
        if (m < NN) {
            float4 v = *(float4*)(sm + r * 128 + c4);
            v.x = fmaxf((v.x + bb.x) * gg.x + be.x, 0.f);
            v.y = fmaxf((v.y + bb.y) * gg.y + be.y, 0.f);
            v.z = fmaxf((v.z + bb.z) * gg.z + be.z, 0.f);
            v.w = fmaxf((v.w + bb.w) * gg.w + be.w, 0.f);
            float4 h = *(const float4*)(hg + (size_t)m * HH + c4);
            float4 xv = *(const float4*)(x1 + (size_t)m * HH + c4);
            float4 o;
            o.x = GW * (v.x + h.x) + (1.0f - GW) * xv.x;
            o.y = GW * (v.y + h.y) + (1.0f - GW) * xv.y;
            o.z = GW * (v.z + h.z) + (1.0f - GW) * xv.z;
            o.w = GW * (v.w + h.w) + (1.0f - GW) * xv.w;
            *(float4*)(y + (size_t)m * HH + c4) = f2tf4(o);
        }
    }
}

// ---- final head GEMM: out = y @ fc_w + fc_b  (N=64)
__global__ void __launch_bounds__(256, 3) gemm_out(
    const float* __restrict__ y, const float* __restrict__ wbuf,
    const float* __restrict__ bias, float* __restrict__ out) {
    extern __shared__ float sm[];
    const int bm = blockIdx.y * BM;
    gemm_core<false>(y, HH, NN, bm, wbuf + WOFF_FC, CC, CC, 0, HH, sm);

    const int tid = threadIdx.x;
    int c4 = (tid & 31) * 4;
    int r0 = tid >> 5;
    if (c4 < CC) {
        float4 bb = *(const float4*)(bias + c4);
#pragma unroll
        for (int j = 0; j < 8; j++) {
            int r = r0 + j * 8;
            int m = bm + r;
            if (m < NN) {
                float4 o = *(float4*)(sm + r * 128 + c4);
                o.x += bb.x; o.y += bb.y; o.z += bb.z; o.w += bb.w;
                *(float4*)(out + (size_t)m * CC + c4) = o;
            }
        }
    }
}

// ============ TF32 split-K kvs: C[128,128] += K_h^T @ V_h ============
#define KVS_SMEM (128 * 128 * 4)

__global__ void __launch_bounds__(256) kvs_tf32_kernel(
    const float* __restrict__ Km, const float* __restrict__ Vm,
    float* __restrict__ Ckvs, int KC) {
    extern __shared__ float sm[];
    float* Ks = sm;             // [32][132]
    float* Vs = sm + 32 * 132;  // [32][132]

    const int tid = threadIdx.x;
    const int wid = tid >> 5;
    const int wr = wid >> 1;
    const int wc = wid & 1;
    const int head = blockIdx.y;
    const float* Kp = Km + head * HH;
    const float* Vp = Vm + head * HH;
    float* Cp = Ckvs + head * HH * HH;
    const int kb = blockIdx.x * KC;
    const int ke = min(kb + KC, NN);
    const float4 z4 = make_float4(0.f, 0.f, 0.f, 0.f);

    wmma::fragment<wmma::accumulator, 16, 16, 8, float> acc[2][4];
#pragma unroll
    for (int i = 0; i < 2; i++)
#pragma unroll
        for (int j = 0; j < 4; j++) wmma::fill_fragment(acc[i][j], 0.0f);

    const int lrow = tid >> 5, lcol = (tid & 31) * 4;

    for (int t = kb; t < ke; t += 32) {
#pragma unroll
        for (int j = 0; j < 4; j++) {
            int kr = t + lrow + j * 8;
            float4 kv = z4, vv = z4;
            if (kr < ke) {
                kv = *(const float4*)(Kp + (size_t)kr * HH2 + lcol);
                vv = *(const float4*)(Vp + (size_t)kr * HH2 + lcol);
            }
            // inputs already tf32-rounded at producer store
            *(float4*)(Ks + (lrow + j * 8) * 132 + lcol) = kv;
            *(float4*)(Vs + (lrow + j * 8) * 132 + lcol) = vv;
        }
        __syncthreads();
#pragma unroll
        for (int ks = 0; ks < 4; ks++) {
            wmma::fragment<wmma::matrix_a, 16, 16, 8, wmma::precision::tf32, wmma::col_major> af[2];
            wmma::load_matrix_sync(af[0], Ks + (ks * 8) * 132 + wr * 32, 132);
            wmma::load_matrix_sync(af[1], Ks + (ks * 8) * 132 + wr * 32 + 16, 132);
#pragma unroll
            for (int ni = 0; ni < 4; ni++) {
                wmma::fragment<wmma::matrix_b, 16, 16, 8, wmma::precision::tf32, wmma::row_major> bf;
                wmma::load_matrix_sync(bf, Vs + (ks * 8) * 132 + wc * 64 + ni * 16, 132);
                wmma::mma_sync(acc[0][ni], af[0], bf, acc[0][ni]);
                wmma::mma_sync(acc[1][ni], af[1], bf, acc[1][ni]);
            }
        }
        __syncthreads();
    }

    float* stg = sm;
#pragma unroll
    for (int mi = 0; mi < 2; mi++)
#pragma unroll
        for (int ni = 0; ni < 4; ni++)
            wmma::store_matrix_sync(stg + (wr * 32 + mi * 16) * 128 + wc * 64 + ni * 16,
                                    acc[mi][ni], 128, wmma::mem_row_major);
    __syncthreads();

    int oc = (tid & 31) * 4;
    int orr = tid >> 5;
#pragma unroll
    for (int j = 0; j < 16; j++) {
        int r = orr + j * 8;
        float4 v = *(float4*)(stg + r * 128 + oc);
        red_add_v4(Cp + r * 128 + oc, v);
    }
}

// ---------------- Q/K reductions ----------------
__global__ void reduce_qk_kernel(const float* __restrict__ q, const float* __restrict__ k,
                                 float* __restrict__ red, float* __restrict__ ksum) {
    __shared__ float sh[256];
    int tid = threadIdx.x;  // blockDim = 256
    size_t total = (size_t)NN * HH2;
    size_t stride = (size_t)gridDim.x * blockDim.x;
    float sq = 0.f, sk = 0.f, kc = 0.f;
    for (size_t i = (size_t)blockIdx.x * 256 + tid; i < total; i += stride) {
        float qv = q[i], kv = k[i];
        sq += qv * qv;
        sk += kv * kv;
        kc += kv;
    }
    atomicAdd(&ksum[tid], kc);
    sh[tid] = sq;
    __syncthreads();
    for (int o = 128; o > 0; o >>= 1) {
        if (tid < o) sh[tid] += sh[tid + o];
        __syncthreads();
    }
    if (tid == 0) atomicAdd(&red[0], sh[0]);
    __syncthreads();
    sh[tid] = sk;
    __syncthreads();
    for (int o = 128; o > 0; o >>= 1) {
        if (tid < o) sh[tid] += sh[tid + o];
        __syncthreads();
    }
    if (tid == 0) atomicAdd(&red[1], sh[0]);
}

// ---------------- attention finalize ----------------
__global__ void attn_finalize_kernel(const float* __restrict__ num, const float* __restrict__ q,
                                     const float* __restrict__ v, const float* __restrict__ ht,
                                     const float* __restrict__ ksum, const float* __restrict__ red,
                                     const float* __restrict__ g, const float* __restrict__ b,
                                     float* __restrict__ x1) {
    __shared__ float ks_s[HH2];
    __shared__ float sh[4];
    int tid = threadIdx.x;  // 128
    ks_s[tid] = ksum[tid];
    ks_s[HH + tid] = ksum[HH + tid];
    float inv = rsqrtf(red[0]) * rsqrtf(red[1]);
    __syncthreads();
    for (int n = blockIdx.x; n < NN; n += gridDim.x) {
        size_t b2 = (size_t)n * HH2;
        float q0 = q[b2 + tid], q1 = q[b2 + HH + tid];
        float s0 = blockReduce128(q0 * ks_s[tid], sh);
        float s1 = blockReduce128(q1 * ks_s[HH + tid], sh);
        float nrm0 = inv * s0 + NFf;
        float nrm1 = inv * s1 + NFf;
        float num0 = inv * num[b2 + tid] + NFf * v[b2 + tid];
        float num1 = inv * num[b2 + HH + tid] + NFf * v[b2 + HH + tid];
        float attn = 0.5f * (num0 / nrm0 + num1 / nrm1);
        float xv = 0.5f * (attn + ht[(size_t)n * HH + tid]);
        float mu = blockReduce128(xv, sh) * (1.0f / 128.0f);
        float d = xv - mu;
        float var = blockReduce128(d * d, sh) * (1.0f / 128.0f);
        float o = d * rsqrtf(var + LN_EPS) * g[tid] + b[tid];
        x1[(size_t)n * HH + tid] = fmaxf(o, 0.0f);
    }
}

// ---------------- CSR build + gather ----------------
__global__ void deg_int_kernel(const int* __restrict__ ei, int* __restrict__ cnt) {
    int i = blockIdx.x * blockDim.x + threadIdx.x;
    int stride = gridDim.x * blockDim.x;
    for (int e = i; e < EE; e += stride) atomicAdd(&cnt[ei[EE + e]], 1);
}

__global__ void f_kernel(const int* __restrict__ cnt, float* __restrict__ f) {
    int i = blockIdx.x * blockDim.x + threadIdx.x;
    int stride = gridDim.x * blockDim.x;
    for (int n = i; n < NN; n += stride)
        f[n] = (cnt[n] > 0) ? rsqrtf((float)cnt[n]) : 0.0f;
}

#define SCAN_NB 98   // ceil(100000/1024)
__global__ void scan_partial(const int* __restrict__ cnt, int* __restrict__ bsum) {
    __shared__ int sh[32];
    int tid = threadIdx.x;  // 1024
    int i = blockIdx.x * 1024 + tid;
    int v = (i < NN) ? cnt[i] : 0;
    unsigned m = 0xffffffffu;
    int s = v;
    s += __shfl_down_sync(m, s, 16);
    s += __shfl_down_sync(m, s, 8);
    s += __shfl_down_sync(m, s, 4);
    s += __shfl_down_sync(m, s, 2);
    s += __shfl_down_sync(m, s, 1);
    if ((tid & 31) == 0) sh[tid >> 5] = s;
    __syncthreads();
    if (tid < 32) {
        int t = sh[tid];
        t += __shfl_down_sync(m, t, 16);
        t += __shfl_down_sync(m, t, 8);
        t += __shfl_down_sync(m, t, 4);
        t += __shfl_down_sync(m, t, 2);
        t += __shfl_down_sync(m, t, 1);
        if (tid == 0) bsum[blockIdx.x] = t;
    }
}

__global__ void scan_bsum(int* __restrict__ bsum) {
    __shared__ int sh[128];
    int tid = threadIdx.x;  // 128
    int v = (tid < SCAN_NB) ? bsum[tid] : 0;
    sh[tid] = v;
    __syncthreads();
    for (int off = 1; off < 128; off <<= 1) {
        int t = (tid >= off) ? sh[tid - off] : 0;
        __syncthreads();
        sh[tid] += t;
        __syncthreads();
    }
    if (tid < SCAN_NB) bsum[tid] = sh[tid] - v;  // exclusive
}

__global__ void scan_final(const int* __restrict__ cnt, const int* __restrict__ bsum,
                           int* __restrict__ rowptr, int* __restrict__ cursor) {
    __shared__ int sh[1024];
    int tid = threadIdx.x;  // 1024
    int i = blockIdx.x * 1024 + tid;
    int v = (i < NN) ? cnt[i] : 0;
    sh[tid] = v;
    __syncthreads();
    for (int off = 1; off < 1024; off <<= 1) {
        int t = (tid >= off) ? sh[tid - off] : 0;
        __syncthreads();
        sh[tid] += t;
        __syncthreads();
    }
    int ex = sh[tid] - v + bsum[blockIdx.x];
    if (i < NN) {
        rowptr[i] = ex;
        cursor[i] = ex;
    }
    if (i == NN - 1) rowptr[NN] = EE;
}

__global__ void fill_csr(const int* __restrict__ ei, int* __restrict__ cursor,
                         int* __restrict__ csr) {
    int i = blockIdx.x * blockDim.x + threadIdx.x;
    int stride = gridDim.x * blockDim.x;
    for (int e = i; e < EE; e += stride) {
        int c = ei[EE + e];
        int pos = atomicAdd(&cursor[c], 1);
        csr[pos] = ei[e];
    }
}

// one warp per node; lane owns 4 channels; tf32-rounded output
__global__ void gather_kernel(const int* __restrict__ rowptr, const int* __restrict__ csr,
                              const float* __restrict__ f, const float* __restrict__ hg,
                              float* __restrict__ agg) {
    int lane = threadIdx.x & 31;
    int w = (blockIdx.x * blockDim.x + threadIdx.x) >> 5;
    if (w >= NN) return;
    int n = w;
    int s = rowptr[n], e = rowptr[n + 1];
    float4 acc = make_float4(0.f, 0.f, 0.f, 0.f);
    for (int j = s; j < e; j++) {
        int r = csr[j];
        float fr = f[r];
        float4 h = *(const float4*)(hg + (size_t)r * HH + lane * 4);
        acc.x += fr * h.x; acc.y += fr * h.y; acc.z += fr * h.z; acc.w += fr * h.w;
    }
    float fc = f[n];
    acc.x *= fc; acc.y *= fc; acc.z *= fc; acc.w *= fc;
    *(float4*)(agg + (size_t)n * HH + lane * 4) = f2tf4(acc);
}

// ---------------- host launcher ----------------
extern "C" void kernel_launch(void* const* d_in, const int* in_sizes, int n_in,
                              void* d_out, int out_size) {
    const float* x = (const float*)d_in[0];
    const int* ei = (const int*)d_in[1];
    const float* t_fc_w = (const float*)d_in[2];
    const float* t_fc_b = (const float*)d_in[3];
    const float* t_ln0_g = (const float*)d_in[4];
    const float* t_ln0_b = (const float*)d_in[5];
    const float* t_wq_w = (const float*)d_in[6];
    const float* t_wq_b = (const float*)d_in[7];
    const float* t_wk_w = (const float*)d_in[8];
    const float* t_wk_b = (const float*)d_in[9];
    const float* t_wv_w = (const float*)d_in[10];
    const float* t_wv_b = (const float*)d_in[11];
    const float* t_ln1_g = (const float*)d_in[12];
    const float* t_ln1_b = (const float*)d_in[13];
    const float* g_fc_w = (const float*)d_in[14];
    const float* g_fc_b = (const float*)d_in[15];
    const float* g_bn0_g = (const float*)d_in[16];
    const float* g_bn0_b = (const float*)d_in[17];
    const float* g_conv_w = (const float*)d_in[18];
    const float* g_conv_b = (const float*)d_in[19];
    const float* g_bn1_g = (const float*)d_in[20];
    const float* g_bn1_b = (const float*)d_in[21];
    const float* fc_w = (const float*)d_in[22];
    const float* fc_b = (const float*)d_in[23];
    float* out = (float*)d_out;

    cudaFuncSetAttribute(gemm_fc_dual, cudaFuncAttributeMaxDynamicSharedMemorySize, GEMM_SMEM);
    cudaFuncSetAttribute(gemm_qkv, cudaFuncAttributeMaxDynamicSharedMemorySize, GEMM_SMEM);
    cudaFuncSetAttribute(gemm_num, cudaFuncAttributeMaxDynamicSharedMemorySize, GEMM_SMEM);
    cudaFuncSetAttribute(gemm_conv_cmb, cudaFuncAttributeMaxDynamicSharedMemorySize, GEMM_SMEM);
    cudaFuncSetAttribute(gemm_out, cudaFuncAttributeMaxDynamicSharedMemorySize, GEMM_SMEM);
    cudaFuncSetAttribute(kvs_tf32_kernel, cudaFuncAttributeMaxDynamicSharedMemorySize, KVS_SMEM);

    float *p_num, *p_ht, *p_hg, *p_q, *p_k, *p_v, *p_x1, *p_agg, *p_y;
    float *p_kvs, *p_red, *p_ksum, *p_f, *p_wbuf;
    int *p_cnt, *p_rowptr, *p_cursor, *p_csr, *p_bsum;
    cudaGetSymbolAddress((void**)&p_num, g_scratch);
    cudaGetSymbolAddress((void**)&p_ht, g_ht);
    cudaGetSymbolAddress((void**)&p_hg, g_hg);
    cudaGetSymbolAddress((void**)&p_q, g_q);
    cudaGetSymbolAddress((void**)&p_k, g_k);
    cudaGetSymbolAddress((void**)&p_v, g_v);
    cudaGetSymbolAddress((void**)&p_x1, g_x1);
    cudaGetSymbolAddress((void**)&p_agg, g_agg);
    cudaGetSymbolAddress((void**)&p_y, g_y);
    cudaGetSymbolAddress((void**)&p_kvs, g_kvs);
    cudaGetSymbolAddress((void**)&p_red, g_red);
    cudaGetSymbolAddress((void**)&p_ksum, g_ksum);
    cudaGetSymbolAddress((void**)&p_f, g_f);
    cudaGetSymbolAddress((void**)&p_wbuf, g_wbuf);
    cudaGetSymbolAddress((void**)&p_cnt, g_cnt);
    cudaGetSymbolAddress((void**)&p_rowptr, g_rowptr);
    cudaGetSymbolAddress((void**)&p_cursor, g_cursor);
    cudaGetSymbolAddress((void**)&p_csr, g_csr);
    cudaGetSymbolAddress((void**)&p_bsum, g_bsum);

    const int GY = (NN + BM - 1) / BM;  // 1563

    // weights -> tf32-rounded copies
    round_weights_kernel<<<248, 256>>>(t_fc_w, g_fc_w, t_wq_w, t_wk_w, t_wv_w,
                                       g_conv_w, fc_w, p_wbuf);

    // ---- Trans + Graph FC (fused over x) ----
    gemm_fc_dual<<<dim3(2, GY), 256, GEMM_SMEM>>>(
        x, p_wbuf, t_fc_b, t_ln0_g, t_ln0_b, g_fc_b, g_bn0_g, g_bn0_b, p_ht, p_hg);

    // ---- QKV fused ----
    gemm_qkv<<<dim3(6, GY), 256, GEMM_SMEM>>>(
        p_ht, p_wbuf, t_wq_b, t_wk_b, t_wv_b, p_q, p_k, p_v);

    zero_kernel<<<1, 256>>>(p_red, 2);
    zero_kernel<<<1, 256>>>(p_ksum, HH2);
    zero_kernel<<<64, 256>>>(p_kvs, 2 * HH * HH);
    reduce_qk_kernel<<<512, 256>>>(p_q, p_k, p_red, p_ksum);

    {
        const int KC = 704;
        const int SPLITS = (NN + KC - 1) / KC;
        dim3 grid(SPLITS, 2);
        kvs_tf32_kernel<<<grid, 256, KVS_SMEM>>>(p_k, p_v, p_kvs, KC);
    }
    round_inplace_kernel<<<32, 256>>>(p_kvs, 2 * HH * HH);

    gemm_num<<<dim3(2, GY), 256, GEMM_SMEM>>>(p_q, p_kvs, p_num);

    attn_finalize_kernel<<<4096, 128>>>(p_num, p_q, p_v, p_ht, p_ksum, p_red,
                                        t_ln1_g, t_ln1_b, p_x1);

    // ---- Graph branch (CSR + gather) ----
    zero_int_kernel<<<128, 256>>>(p_cnt, NN);
    deg_int_kernel<<<2048, 256>>>(ei, p_cnt);
    f_kernel<<<128, 256>>>(p_cnt, p_f);
    scan_partial<<<SCAN_NB, 1024>>>(p_cnt, p_bsum);
    scan_bsum<<<1, 128>>>(p_bsum);
    scan_final<<<SCAN_NB, 1024>>>(p_cnt, p_bsum, p_rowptr, p_cursor);
    fill_csr<<<2048, 256>>>(ei, p_cursor, p_csr);
    gather_kernel<<<(NN * 32 + 255) / 256, 256>>>(p_rowptr, p_csr, p_f, p_hg, p_agg);

    // ---- combine + head ----
    gemm_conv_cmb<<<dim3(1, GY), 256, GEMM_SMEM>>>(
        p_agg, p_wbuf, g_conv_b, g_bn1_g, g_bn1_b, p_hg, p_x1, p_y);

    gemm_out<<<dim3(1, GY), 256, GEMM_SMEM>>>(p_y, p_wbuf, fc_b, out);
}

// round 8
// speedup vs baseline: 1.9085x; 1.0559x over previous
#include <cuda_runtime.h>
#include <cuda_bf16.h>
#include <mma.h>
#include <math.h>

using namespace nvcuda;

// Problem constants
#define NN 100000
#define FF 512
#define HH 128
#define HH2 256
#define EE 1600000
#define CC 64
#define NFf 100000.0f
#define LN_EPS 1e-5f
#define GW 0.8f

// ---------------- scratch (device globals; allocation-free) ----------------
__device__ float g_ht[(size_t)NN * HH];
__device__ float g_hg[(size_t)NN * HH];
__device__ float g_q[(size_t)NN * HH2];
__device__ float g_k[(size_t)NN * HH2];
__device__ float g_v[(size_t)NN * HH2];
__device__ float g_x1[(size_t)NN * HH];
__device__ float g_agg[(size_t)NN * HH];
__device__ float g_y[(size_t)NN * HH];
__device__ float g_kvs2[HH2 * HH2];   // block-diag [kvs0 0; 0 kvs1]
__device__ float g_red[2];            // sum q^2, sum k^2
__device__ float g_ksum[HH2];         // column sums of k
// pre-rounded (tf32) weights
#define WOFF_T 0
#define WOFF_G 65536
#define WOFF_Q 131072
#define WOFF_K 163840
#define WOFF_V 196608
#define WOFF_CONV 229376
#define WOFF_FC 245760
__device__ float g_wbuf[253952];
// CSR machinery
__device__ int g_cnt[NN];
__device__ int g_rowptr[NN + 1];
__device__ int g_cursor[NN];
__device__ int g_csr[EE];
__device__ float g_f[NN];
__device__ int g_bsum[128];

// ---------------- utility ----------------
__global__ void zero_kernel(float* p, size_t n) {
    size_t i = (size_t)blockIdx.x * blockDim.x + threadIdx.x;
    size_t stride = (size_t)gridDim.x * blockDim.x;
    for (; i < n; i += stride) p[i] = 0.0f;
}
__global__ void zero_int_kernel(int* p, size_t n) {
    size_t i = (size_t)blockIdx.x * blockDim.x + threadIdx.x;
    size_t stride = (size_t)gridDim.x * blockDim.x;
    for (; i < n; i += stride) p[i] = 0;
}

__device__ __forceinline__ float warpAllSum(float v) {
    unsigned m = 0xffffffffu;
    v += __shfl_xor_sync(m, v, 16);
    v += __shfl_xor_sync(m, v, 8);
    v += __shfl_xor_sync(m, v, 4);
    v += __shfl_xor_sync(m, v, 2);
    v += __shfl_xor_sync(m, v, 1);
    return v;
}

__device__ __forceinline__ float f2tf(float x) {
    float r;
    asm("cvt.rna.tf32.f32 %0, %1;" : "=f"(r) : "f"(x));
    return r;
}
__device__ __forceinline__ float4 f2tf4(float4 v) {
    v.x = f2tf(v.x); v.y = f2tf(v.y); v.z = f2tf(v.z); v.w = f2tf(v.w);
    return v;
}
__device__ __forceinline__ void red_add_v4(float* p, float4 v) {
    asm volatile("red.global.add.v4.f32 [%0], {%1,%2,%3,%4};"
                 :: "l"(p), "f"(v.x), "f"(v.y), "f"(v.z), "f"(v.w) : "memory");
}
__device__ __forceinline__ void cp16(float* smem, const float* gmem, bool pred) {
    unsigned saddr = (unsigned)__cvta_generic_to_shared(smem);
    int sz = pred ? 16 : 0;
    asm volatile("cp.async.cg.shared.global [%0], [%1], 16, %2;"
                 :: "r"(saddr), "l"(gmem), "r"(sz));
}

// weight pre-rounding
__global__ void round_weights_kernel(const float* __restrict__ wt, const float* __restrict__ wg,
                                     const float* __restrict__ wq, const float* __restrict__ wk,
                                     const float* __restrict__ wv, const float* __restrict__ wc,
                                     const float* __restrict__ wf, float* __restrict__ dst) {
    int i = blockIdx.x * blockDim.x + threadIdx.x;
    int stride = gridDim.x * blockDim.x;
    for (int j = i; j < 253952; j += stride) {
        float v;
        if (j < WOFF_G) v = wt[j - WOFF_T];
        else if (j < WOFF_Q) v = wg[j - WOFF_G];
        else if (j < WOFF_K) v = wq[j - WOFF_Q];
        else if (j < WOFF_V) v = wk[j - WOFF_K];
        else if (j < WOFF_CONV) v = wv[j - WOFF_V];
        else if (j < WOFF_FC) v = wc[j - WOFF_CONV];
        else v = wf[j - WOFF_FC];
        dst[j] = f2tf(v);
    }
}

__global__ void round_inplace_kernel(float* p, int n) {
    int i = blockIdx.x * blockDim.x + threadIdx.x;
    int stride = gridDim.x * blockDim.x;
    for (int j = i; j < n; j += stride) p[j] = f2tf(p[j]);
}

// ============ TF32 tensor GEMM core: BM=64, BN templated (128/256), BK=32 ============
#define BM 64
#define AS_LD 36
#define A_STAGE (BM * AS_LD)   // 2304 floats

template <int BNT, bool CVTA>
__device__ __forceinline__ void gemm_core(
    const float* __restrict__ A, int lda, int M, int bm,
    const float* __restrict__ B, int ldb, int N, int bn,
    int K, float* sm) {
    constexpr int BS_LD = BNT + 4;
    constexpr int B_STAGE = 32 * BS_LD;
    constexpr int STG = A_STAGE + B_STAGE;
    constexpr int WCW = (BNT == 128) ? 32 : 64;   // warp col width
    constexpr int NFR = WCW / 16;
    constexpr int CPR = BNT / 4;                  // float4 cols per B row
    constexpr int BITER = BNT / 32;               // B loader iterations

    const int tid = threadIdx.x;
    const int wid = tid >> 5;
    const int wr = wid >> 2;  // 0..1
    const int wc = wid & 3;   // 0..3

    wmma::fragment<wmma::accumulator, 16, 16, 8, float> acc[2][NFR];
#pragma unroll
    for (int i = 0; i < 2; i++)
#pragma unroll
        for (int j = 0; j < NFR; j++) wmma::fill_fragment(acc[i][j], 0.0f);

    const int T = K >> 5;

    auto load_stage = [&](int t, int s) {
        const int k0 = t << 5;
        float* sA = sm + s * STG;
        float* sB = sm + s * STG + A_STAGE;
#pragma unroll
        for (int j = 0; j < 2; j++) {
            int idx = tid + j * 256;        // 64x8 float4
            int r = idx >> 3, c4 = idx & 7;
            bool ok = (bm + r) < M;
            const float* src = A + (size_t)(ok ? bm + r : 0) * lda + k0 + c4 * 4;
            cp16(sA + r * AS_LD + c4 * 4, src, ok);
        }
#pragma unroll
        for (int j = 0; j < BITER; j++) {
            int idx = tid + j * 256;        // 32 x CPR float4
            int r = idx / CPR, c4 = idx % CPR;
            bool ok = (bn + c4 * 4) < N;
            const float* src = B + (size_t)(k0 + r) * ldb + bn + (ok ? c4 * 4 : 0);
            cp16(sB + r * BS_LD + c4 * 4, src, ok);
        }
        asm volatile("cp.async.commit_group;");
    };

    load_stage(0, 0);

    for (int t = 0; t < T; t++) {
        const int s = t & 1;
        if (t + 1 < T) {
            load_stage(t + 1, s ^ 1);
            asm volatile("cp.async.wait_group 1;");
        } else {
            asm volatile("cp.async.wait_group 0;");
        }
        __syncthreads();
        const float* sA = sm + s * STG;
        const float* sB = sm + s * STG + A_STAGE;
#pragma unroll
        for (int ks = 0; ks < 4; ks++) {
            wmma::fragment<wmma::matrix_a, 16, 16, 8, wmma::precision::tf32, wmma::row_major> af[2];
#pragma unroll
            for (int mi = 0; mi < 2; mi++) {
                wmma::load_matrix_sync(af[mi], sA + (wr * 32 + mi * 16) * AS_LD + ks * 8, AS_LD);
                if (CVTA) {
#pragma unroll
                    for (int e = 0; e < af[mi].num_elements; e++) af[mi].x[e] = f2tf(af[mi].x[e]);
                }
            }
#pragma unroll
            for (int ni = 0; ni < NFR; ni++) {
                wmma::fragment<wmma::matrix_b, 16, 16, 8, wmma::precision::tf32, wmma::row_major> bf;
                wmma::load_matrix_sync(bf, sB + (ks * 8) * BS_LD + wc * WCW + ni * 16, BS_LD);
                wmma::mma_sync(acc[0][ni], af[0], bf, acc[0][ni]);
                wmma::mma_sync(acc[1][ni], af[1], bf, acc[1][ni]);
            }
        }
        __syncthreads();
    }

    // stage result tile to sm[0 .. 64*BNT)
#pragma unroll
    for (int mi = 0; mi < 2; mi++)
#pragma unroll
        for (int ni = 0; ni < NFR; ni++)
            wmma::store_matrix_sync(sm + (wr * 32 + mi * 16) * BNT + wc * WCW + ni * 16,
                                    acc[mi][ni], BNT, wmma::mem_row_major);
    __syncthreads();
}

#define GEMM_SMEM128 (2 * (A_STAGE + 32 * 132) * 4)   // 52224
#define GEMM_SMEM256 (2 * (A_STAGE + 32 * 260) * 4)   // 84992

// ---- fused x-GEMM: blockIdx.x==0 -> ht = relu(LN(x@Wt+bt)); ==1 -> hg = relu(BN(x@Wg+bg))
__global__ void __launch_bounds__(256, 3) gemm_fc_dual(
    const float* __restrict__ x, const float* __restrict__ wbuf,
    const float* __restrict__ bt, const float* __restrict__ ln_g, const float* __restrict__ ln_b,
    const float* __restrict__ bg, const float* __restrict__ bn_g, const float* __restrict__ bn_b,
    float* __restrict__ ht, float* __restrict__ hg) {
    extern __shared__ float sm[];
    const int which = blockIdx.x;
    const int bm = blockIdx.y * BM;
    const float* B = wbuf + (which ? WOFF_G : WOFF_T);
    gemm_core<128, true>(x, FF, NN, bm, B, HH, HH, 0, FF, sm);

    const int tid = threadIdx.x;
    const int wid = tid >> 5;
    const int lane = tid & 31;

    if (which == 0) {
        float4 bb = *(const float4*)(bt + lane * 4);
        float4 gg = *(const float4*)(ln_g + lane * 4);
        float4 be = *(const float4*)(ln_b + lane * 4);
#pragma unroll
        for (int i = 0; i < 8; i++) {
            int r = wid * 8 + i;
            int m = bm + r;
            float4 v = *(float4*)(sm + r * 128 + lane * 4);
            v.x += bb.x; v.y += bb.y; v.z += bb.z; v.w += bb.w;
            float mu = warpAllSum(v.x + v.y + v.z + v.w) * (1.0f / 128.0f);
            float4 d = make_float4(v.x - mu, v.y - mu, v.z - mu, v.w - mu);
            float var = warpAllSum(d.x * d.x + d.y * d.y + d.z * d.z + d.w * d.w) * (1.0f / 128.0f);
            float rs = rsqrtf(var + LN_EPS);
            float4 o;
            o.x = fmaxf(d.x * rs * gg.x + be.x, 0.f);
            o.y = fmaxf(d.y * rs * gg.y + be.y, 0.f);
            o.z = fmaxf(d.z * rs * gg.z + be.z, 0.f);
            o.w = fmaxf(d.w * rs * gg.w + be.w, 0.f);
            if (m < NN) *(float4*)(ht + (size_t)m * HH + lane * 4) = f2tf4(o);
        }
    } else {
        int c4 = lane * 4;
        int r0 = wid;
        const float sbn = rsqrtf(1.0f + LN_EPS);
        float4 bb = *(const float4*)(bg + c4);
        float4 gg = *(const float4*)(bn_g + c4);
        float4 be = *(const float4*)(bn_b + c4);
        gg.x *= sbn; gg.y *= sbn; gg.z *= sbn; gg.w *= sbn;
#pragma unroll
        for (int j = 0; j < 8; j++) {
            int r = r0 + j * 8;
            int m = bm + r;
            if (m < NN) {
                float4 v = *(float4*)(sm + r * 128 + c4);
                float4 o;
                o.x = fmaxf((v.x + bb.x) * gg.x + be.x, 0.f);
                o.y = fmaxf((v.y + bb.y) * gg.y + be.y, 0.f);
                o.z = fmaxf((v.z + bb.z) * gg.z + be.z, 0.f);
                o.w = fmaxf((v.w + bb.w) * gg.w + be.w, 0.f);
                *(float4*)(hg + (size_t)m * HH + c4) = f2tf4(o);
            }
        }
    }
}

// ---- fused QKV + norm/ksum reductions in epilogue ----
__global__ void __launch_bounds__(256, 3) gemm_qkv(
    const float* __restrict__ ht, const float* __restrict__ wbuf,
    const float* __restrict__ bq, const float* __restrict__ bk, const float* __restrict__ bv,
    float* __restrict__ q, float* __restrict__ k, float* __restrict__ v,
    float* __restrict__ red, float* __restrict__ ksum) {
    extern __shared__ float sm[];
    __shared__ float rsh[8];
    __shared__ float ks_s[128];
    const int sel = blockIdx.x >> 1;
    const int bn = (blockIdx.x & 1) * 128;
    const int bm = blockIdx.y * BM;
    const float* B = wbuf + (sel == 0 ? WOFF_Q : (sel == 1 ? WOFF_K : WOFF_V));
    const float* bias = (sel == 0 ? bq : (sel == 1 ? bk : bv));
    float* C = (sel == 0 ? q : (sel == 1 ? k : v));
    gemm_core<128, false>(ht, HH, NN, bm, B, HH2, HH2, bn, HH, sm);

    const int tid = threadIdx.x;
    int c4 = (tid & 31) * 4;
    int r0 = tid >> 5;
    float4 bb = *(const float4*)(bias + bn + c4);

    if (sel == 1 && tid < 128) ks_s[tid] = 0.0f;
    __syncthreads();

    float sq = 0.0f;
    float4 cs = make_float4(0.f, 0.f, 0.f, 0.f);
#pragma unroll
    for (int j = 0; j < 8; j++) {
        int r = r0 + j * 8;
        int m = bm + r;
        if (m < NN) {
            float4 o = *(float4*)(sm + r * 128 + c4);
            o.x += bb.x; o.y += bb.y; o.z += bb.z; o.w += bb.w;
            if (sel < 2) sq += o.x * o.x + o.y * o.y + o.z * o.z + o.w * o.w;
            if (sel == 1) { cs.x += o.x; cs.y += o.y; cs.z += o.z; cs.w += o.w; }
            *(float4*)(C + (size_t)m * HH2 + bn + c4) = f2tf4(o);
        }
    }

    if (sel < 2) {
        float ws = warpAllSum(sq);
        if ((tid & 31) == 0) rsh[tid >> 5] = ws;
        __syncthreads();
        if (tid == 0) {
            float s = 0.f;
#pragma unroll
            for (int i = 0; i < 8; i++) s += rsh[i];
            atomicAdd(&red[sel], s);
        }
    }
    if (sel == 1) {
        atomicAdd(&ks_s[c4 + 0], cs.x);
        atomicAdd(&ks_s[c4 + 1], cs.y);
        atomicAdd(&ks_s[c4 + 2], cs.z);
        atomicAdd(&ks_s[c4 + 3], cs.w);
        __syncthreads();
        if (tid < 128) atomicAdd(&ksum[bn + tid], ks_s[tid]);
    }
}

// ---- num GEMM over block-diag kvs2 + FULL fused finalize (both heads) -> x1 ----
__global__ void __launch_bounds__(256, 2) gemm_num_fin(
    const float* __restrict__ q, const float* __restrict__ kvs2,
    const float* __restrict__ v, const float* __restrict__ ht,
    const float* __restrict__ ksum, const float* __restrict__ red,
    const float* __restrict__ ln_g, const float* __restrict__ ln_b,
    float* __restrict__ x1) {
    extern __shared__ float sm[];
    const int bm = blockIdx.y * BM;
    gemm_core<256, false>(q, HH2, NN, bm, kvs2, HH2, HH2, 0, HH2, sm);

    const int tid = threadIdx.x;
    const int wid = tid >> 5;
    const int lane = tid & 31;
    const float inv = rsqrtf(red[0]) * rsqrtf(red[1]);

    // ksum slice for normalizer dot: lane owns cols lane*8 .. +7
    float4 ka = *(const float4*)(ksum + lane * 8);
    float4 kb = *(const float4*)(ksum + lane * 8 + 4);
    float4 gg = *(const float4*)(ln_g + lane * 4);
    float4 be = *(const float4*)(ln_b + lane * 4);

#pragma unroll
    for (int i = 0; i < 8; i++) {
        int r = wid * 8 + i;
        int m = bm + r;
        if (m >= NN) continue;  // uniform per warp
        // normalizer: s_h = dot(q[m, h*128: h*128+128], ksum[h*128:...])
        const float* qrow = q + (size_t)m * HH2 + lane * 8;
        float4 qa = *(const float4*)(qrow);
        float4 qb = *(const float4*)(qrow + 4);
        float part = qa.x * ka.x + qa.y * ka.y + qa.z * ka.z + qa.w * ka.w
                   + qb.x * kb.x + qb.y * kb.y + qb.z * kb.z + qb.w * kb.w;
        float s0 = warpAllSum(lane < 16 ? part : 0.0f);
        float s1 = warpAllSum(lane >= 16 ? part : 0.0f);
        float nrm0 = inv * s0 + NFf;
        float nrm1 = inv * s1 + NFf;

        float4 n0 = *(float4*)(sm + r * 256 + lane * 4);
        float4 n1 = *(float4*)(sm + r * 256 + 128 + lane * 4);
        float4 v0 = *(const float4*)(v + (size_t)m * HH2 + lane * 4);
        float4 v1 = *(const float4*)(v + (size_t)m * HH2 + 128 + lane * 4);
        float4 hv = *(const float4*)(ht + (size_t)m * HH + lane * 4);

        float4 xv;
        xv.x = 0.5f * (0.5f * ((inv * n0.x + NFf * v0.x) / nrm0 + (inv * n1.x + NFf * v1.x) / nrm1) + hv.x);
        xv.y = 0.5f * (0.5f * ((inv * n0.y + NFf * v0.y) / nrm0 + (inv * n1.y + NFf * v1.y) / nrm1) + hv.y);
        xv.z = 0.5f * (0.5f * ((inv * n0.z + NFf * v0.z) / nrm0 + (inv * n1.z + NFf * v1.z) / nrm1) + hv.z);
        xv.w = 0.5f * (0.5f * ((inv * n0.w + NFf * v0.w) / nrm0 + (inv * n1.w + NFf * v1.w) / nrm1) + hv.w);

        float mu = warpAllSum(xv.x + xv.y + xv.z + xv.w) * (1.0f / 128.0f);
        float4 d = make_float4(xv.x - mu, xv.y - mu, xv.z - mu, xv.w - mu);
        float var = warpAllSum(d.x * d.x + d.y * d.y + d.z * d.z + d.w * d.w) * (1.0f / 128.0f);
        float rs = rsqrtf(var + LN_EPS);
        float4 o;
        o.x = fmaxf(d.x * rs * gg.x + be.x, 0.f);
        o.y = fmaxf(d.y * rs * gg.y + be.y, 0.f);
        o.z = fmaxf(d.z * rs * gg.z + be.z, 0.f);
        o.w = fmaxf(d.w * rs * gg.w + be.w, 0.f);
        *(float4*)(x1 + (size_t)m * HH + lane * 4) = o;
    }
}

// ---- conv GEMM + BN + relu + residual + mix epilogue -> y (rounded)
__global__ void __launch_bounds__(256, 3) gemm_conv_cmb(
    const float* __restrict__ agg, const float* __restrict__ wbuf,
    const float* __restrict__ bias, const float* __restrict__ bn_g, const float* __restrict__ bn_b,
    const float* __restrict__ hg, const float* __restrict__ x1,
    float* __restrict__ y) {
    extern __shared__ float sm[];
    const int bm = blockIdx.y * BM;
    gemm_core<128, false>(agg, HH, NN, bm, wbuf + WOFF_CONV, HH, HH, 0, HH, sm);

    const int tid = threadIdx.x;
    int c4 = (tid & 31) * 4;
    int r0 = tid >> 5;
    const float sbn = rsqrtf(1.0f + LN_EPS);
    float4 bb = *(const float4*)(bias + c4);
    float4 gg = *(const float4*)(bn_g + c4);
    float4 be = *(const float4*)(bn_b + c4);
    gg.x *= sbn; gg.y *= sbn; gg.z *= sbn; gg.w *= sbn;
#pragma unroll
    for (int j = 0; j < 8; j++) {
        int r = r0 + j * 8;
        int m = bm + r;
        if (m < NN) {
            float4 v = *(float4*)(sm + r * 128 + c4);
            v.x = fmaxf((v.x + bb.x) * gg.x + be.x, 0.f);
            v.y = fmaxf((v.y + bb.y) * gg.y + be.y, 0.f);
            v.z = fmaxf((v.z + bb.z) * gg.z + be.z, 0.f);
            v.w = fmaxf((v.w + bb.w) * gg.w + be.w, 0.f);
            float4 h = *(const float4*)(hg + (size_t)m * HH + c4);
            float4 xv = *(const float4*)(x1 + (size_t)m * HH + c4);
            float4 o;
            o.x = GW * (v.x + h.x) + (1.0f - GW) * xv.x;
            o.y = GW * (v.y + h.y) + (1.0f - GW) * xv.y;
            o.z = GW * (v.z + h.z) + (1.0f - GW) * xv.z;
            o.w = GW * (v.w + h.w) + (1.0f - GW) * xv.w;
            *(float4*)(y + (size_t)m * HH + c4) = f2tf4(o);
        }
    }
}

// ---- final head GEMM: out = y @ fc_w + fc_b  (N=64)
__global__ void __launch_bounds__(256, 3) gemm_out(
    const float* __restrict__ y, const float* __restrict__ wbuf,
    const float* __restrict__ bias, float* __restrict__ out) {
    extern __shared__ float sm[];
    const int bm = blockIdx.y * BM;
    gemm_core<128, false>(y, HH, NN, bm, wbuf + WOFF_FC, CC, CC, 0, HH, sm);

    const int tid = threadIdx.x;
    int c4 = (tid & 31) * 4;
    int r0 = tid >> 5;
    if (c4 < CC) {
        float4 bb = *(const float4*)(bias + c4);
#pragma unroll
        for (int j = 0; j < 8; j++) {
            int r = r0 + j * 8;
            int m = bm + r;
            if (m < NN) {
                float4 o = *(float4*)(sm + r * 128 + c4);
                o.x += bb.x; o.y += bb.y; o.z += bb.z; o.w += bb.w;
                *(float4*)(out + (size_t)m * CC + c4) = o;
            }
        }
    }
}

// ============ TF32 split-K kvs -> block-diag kvs2 ============
#define KVS_SMEM (128 * 128 * 4)

__global__ void __launch_bounds__(256) kvs_tf32_kernel(
    const float* __restrict__ Km, const float* __restrict__ Vm,
    float* __restrict__ kvs2, int KC) {
    extern __shared__ float sm[];
    float* Ks = sm;             // [32][132]
    float* Vs = sm + 32 * 132;  // [32][132]

    const int tid = threadIdx.x;
    const int wid = tid >> 5;
    const int wr = wid >> 1;
    const int wc = wid & 1;
    const int head = blockIdx.y;
    const float* Kp = Km + head * HH;
    const float* Vp = Vm + head * HH;
    float* Cp = kvs2 + head * (128 * HH2 + 128);  // diag block origin
    const int kb = blockIdx.x * KC;
    const int ke = min(kb + KC, NN);
    const float4 z4 = make_float4(0.f, 0.f, 0.f, 0.f);

    wmma::fragment<wmma::accumulator, 16, 16, 8, float> acc[2][4];
#pragma unroll
    for (int i = 0; i < 2; i++)
#pragma unroll
        for (int j = 0; j < 4; j++) wmma::fill_fragment(acc[i][j], 0.0f);

    const int lrow = tid >> 5, lcol = (tid & 31) * 4;

    for (int t = kb; t < ke; t += 32) {
#pragma unroll
        for (int j = 0; j < 4; j++) {
            int kr = t + lrow + j * 8;
            float4 kv = z4, vv = z4;
            if (kr < ke) {
                kv = *(const float4*)(Kp + (size_t)kr * HH2 + lcol);
                vv = *(const float4*)(Vp + (size_t)kr * HH2 + lcol);
            }
            *(float4*)(Ks + (lrow + j * 8) * 132 + lcol) = kv;
            *(float4*)(Vs + (lrow + j * 8) * 132 + lcol) = vv;
        }
        __syncthreads();
#pragma unroll
        for (int ks = 0; ks < 4; ks++) {
            wmma::fragment<wmma::matrix_a, 16, 16, 8, wmma::precision::tf32, wmma::col_major> af[2];
            wmma::load_matrix_sync(af[0], Ks + (ks * 8) * 132 + wr * 32, 132);
            wmma::load_matrix_sync(af[1], Ks + (ks * 8) * 132 + wr * 32 + 16, 132);
#pragma unroll
            for (int ni = 0; ni < 4; ni++) {
                wmma::fragment<wmma::matrix_b, 16, 16, 8, wmma::precision::tf32, wmma::row_major> bf;
                wmma::load_matrix_sync(bf, Vs + (ks * 8) * 132 + wc * 64 + ni * 16, 132);
                wmma::mma_sync(acc[0][ni], af[0], bf, acc[0][ni]);
                wmma::mma_sync(acc[1][ni], af[1], bf, acc[1][ni]);
            }
        }
        __syncthreads();
    }

    float* stg = sm;
#pragma unroll
    for (int mi = 0; mi < 2; mi++)
#pragma unroll
        for (int ni = 0; ni < 4; ni++)
            wmma::store_matrix_sync(stg + (wr * 32 + mi * 16) * 128 + wc * 64 + ni * 16,
                                    acc[mi][ni], 128, wmma::mem_row_major);
    __syncthreads();

    int oc = (tid & 31) * 4;
    int orr = tid >> 5;
#pragma unroll
    for (int j = 0; j < 16; j++) {
        int r = orr + j * 8;
        float4 v = *(float4*)(stg + r * 128 + oc);
        red_add_v4(Cp + (size_t)r * HH2 + oc, v);
    }
}

// ---------------- CSR build + gather ----------------
__global__ void deg_int_kernel(const int* __restrict__ ei, int* __restrict__ cnt) {
    int i = blockIdx.x * blockDim.x + threadIdx.x;
    int stride = gridDim.x * blockDim.x;
    for (int e = i; e < EE; e += stride) atomicAdd(&cnt[ei[EE + e]], 1);
}

__global__ void f_kernel(const int* __restrict__ cnt, float* __restrict__ f) {
    int i = blockIdx.x * blockDim.x + threadIdx.x;
    int stride = gridDim.x * blockDim.x;
    for (int n = i; n < NN; n += stride)
        f[n] = (cnt[n] > 0) ? rsqrtf((float)cnt[n]) : 0.0f;
}

#define SCAN_NB 98   // ceil(100000/1024)
__global__ void scan_partial(const int* __restrict__ cnt, int* __restrict__ bsum) {
    __shared__ int sh[32];
    int tid = threadIdx.x;  // 1024
    int i = blockIdx.x * 1024 + tid;
    int v = (i < NN) ? cnt[i] : 0;
    unsigned m = 0xffffffffu;
    int s = v;
    s += __shfl_down_sync(m, s, 16);
    s += __shfl_down_sync(m, s, 8);
    s += __shfl_down_sync(m, s, 4);
    s += __shfl_down_sync(m, s, 2);
    s += __shfl_down_sync(m, s, 1);
    if ((tid & 31) == 0) sh[tid >> 5] = s;
    __syncthreads();
    if (tid < 32) {
        int t = sh[tid];
        t += __shfl_down_sync(m, t, 16);
        t += __shfl_down_sync(m, t, 8);
        t += __shfl_down_sync(m, t, 4);
        t += __shfl_down_sync(m, t, 2);
        t += __shfl_down_sync(m, t, 1);
        if (tid == 0) bsum[blockIdx.x] = t;
    }
}

__global__ void scan_bsum(int* __restrict__ bsum) {
    __shared__ int sh[128];
    int tid = threadIdx.x;  // 128
    int v = (tid < SCAN_NB) ? bsum[tid] : 0;
    sh[tid] = v;
    __syncthreads();
    for (int off = 1; off < 128; off <<= 1) {
        int t = (tid >= off) ? sh[tid - off] : 0;
        __syncthreads();
        sh[tid] += t;
        __syncthreads();
    }
    if (tid < SCAN_NB) bsum[tid] = sh[tid] - v;  // exclusive
}

__global__ void scan_final(const int* __restrict__ cnt, const int* __restrict__ bsum,
                           int* __restrict__ rowptr, int* __restrict__ cursor) {
    __shared__ int sh[1024];
    int tid = threadIdx.x;  // 1024
    int i = blockIdx.x * 1024 + tid;
    int v = (i < NN) ? cnt[i] : 0;
    sh[tid] = v;
    __syncthreads();
    for (int off = 1; off < 1024; off <<= 1) {
        int t = (tid >= off) ? sh[tid - off] : 0;
        __syncthreads();
        sh[tid] += t;
        __syncthreads();
    }
    int ex = sh[tid] - v + bsum[blockIdx.x];
    if (i < NN) {
        rowptr[i] = ex;
        cursor[i] = ex;
    }
    if (i == NN - 1) rowptr[NN] = EE;
}

__global__ void fill_csr(const int* __restrict__ ei, int* __restrict__ cursor,
                         int* __restrict__ csr) {
    int i = blockIdx.x * blockDim.x + threadIdx.x;
    int stride = gridDim.x * blockDim.x;
    for (int e = i; e < EE; e += stride) {
        int c = ei[EE + e];
        int pos = atomicAdd(&cursor[c], 1);
        csr[pos] = ei[e];
    }
}

// one warp per node; lane owns 4 channels; tf32-rounded output
__global__ void gather_kernel(const int* __restrict__ rowptr, const int* __restrict__ csr,
                              const float* __restrict__ f, const float* __restrict__ hg,
                              float* __restrict__ agg) {
    int lane = threadIdx.x & 31;
    int w = (blockIdx.x * blockDim.x + threadIdx.x) >> 5;
    if (w >= NN) return;
    int n = w;
    int s = rowptr[n], e = rowptr[n + 1];
    float4 acc = make_float4(0.f, 0.f, 0.f, 0.f);
    for (int j = s; j < e; j++) {
        int r = csr[j];
        float fr = f[r];
        float4 h = *(const float4*)(hg + (size_t)r * HH + lane * 4);
        acc.x += fr * h.x; acc.y += fr * h.y; acc.z += fr * h.z; acc.w += fr * h.w;
    }
    float fc = f[n];
    acc.x *= fc; acc.y *= fc; acc.z *= fc; acc.w *= fc;
    *(float4*)(agg + (size_t)n * HH + lane * 4) = f2tf4(acc);
}

// ---------------- host launcher ----------------
extern "C" void kernel_launch(void* const* d_in, const int* in_sizes, int n_in,
                              void* d_out, int out_size) {
    const float* x = (const float*)d_in[0];
    const int* ei = (const int*)d_in[1];
    const float* t_fc_w = (const float*)d_in[2];
    const float* t_fc_b = (const float*)d_in[3];
    const float* t_ln0_g = (const float*)d_in[4];
    const float* t_ln0_b = (const float*)d_in[5];
    const float* t_wq_w = (const float*)d_in[6];
    const float* t_wq_b = (const float*)d_in[7];
    const float* t_wk_w = (const float*)d_in[8];
    const float* t_wk_b = (const float*)d_in[9];
    const float* t_wv_w = (const float*)d_in[10];
    const float* t_wv_b = (const float*)d_in[11];
    const float* t_ln1_g = (const float*)d_in[12];
    const float* t_ln1_b = (const float*)d_in[13];
    const float* g_fc_w = (const float*)d_in[14];
    const float* g_fc_b = (const float*)d_in[15];
    const float* g_bn0_g = (const float*)d_in[16];
    const float* g_bn0_b = (const float*)d_in[17];
    const float* g_conv_w = (const float*)d_in[18];
    const float* g_conv_b = (const float*)d_in[19];
    const float* g_bn1_g = (const float*)d_in[20];
    const float* g_bn1_b = (const float*)d_in[21];
    const float* fc_w = (const float*)d_in[22];
    const float* fc_b = (const float*)d_in[23];
    float* out = (float*)d_out;

    cudaFuncSetAttribute(gemm_fc_dual, cudaFuncAttributeMaxDynamicSharedMemorySize, GEMM_SMEM128);
    cudaFuncSetAttribute(gemm_qkv, cudaFuncAttributeMaxDynamicSharedMemorySize, GEMM_SMEM128);
    cudaFuncSetAttribute(gemm_num_fin, cudaFuncAttributeMaxDynamicSharedMemorySize, GEMM_SMEM256);
    cudaFuncSetAttribute(gemm_conv_cmb, cudaFuncAttributeMaxDynamicSharedMemorySize, GEMM_SMEM128);
    cudaFuncSetAttribute(gemm_out, cudaFuncAttributeMaxDynamicSharedMemorySize, GEMM_SMEM128);
    cudaFuncSetAttribute(kvs_tf32_kernel, cudaFuncAttributeMaxDynamicSharedMemorySize, KVS_SMEM);

    float *p_ht, *p_hg, *p_q, *p_k, *p_v, *p_x1, *p_agg, *p_y;
    float *p_kvs2, *p_red, *p_ksum, *p_f, *p_wbuf;
    int *p_cnt, *p_rowptr, *p_cursor, *p_csr, *p_bsum;
    cudaGetSymbolAddress((void**)&p_ht, g_ht);
    cudaGetSymbolAddress((void**)&p_hg, g_hg);
    cudaGetSymbolAddress((void**)&p_q, g_q);
    cudaGetSymbolAddress((void**)&p_k, g_k);
    cudaGetSymbolAddress((void**)&p_v, g_v);
    cudaGetSymbolAddress((void**)&p_x1, g_x1);
    cudaGetSymbolAddress((void**)&p_agg, g_agg);
    cudaGetSymbolAddress((void**)&p_y, g_y);
    cudaGetSymbolAddress((void**)&p_kvs2, g_kvs2);
    cudaGetSymbolAddress((void**)&p_red, g_red);
    cudaGetSymbolAddress((void**)&p_ksum, g_ksum);
    cudaGetSymbolAddress((void**)&p_f, g_f);
    cudaGetSymbolAddress((void**)&p_wbuf, g_wbuf);
    cudaGetSymbolAddress((void**)&p_cnt, g_cnt);
    cudaGetSymbolAddress((void**)&p_rowptr, g_rowptr);
    cudaGetSymbolAddress((void**)&p_cursor, g_cursor);
    cudaGetSymbolAddress((void**)&p_csr, g_csr);
    cudaGetSymbolAddress((void**)&p_bsum, g_bsum);

    const int GY = (NN + BM - 1) / BM;  // 1563

    // weights -> tf32-rounded copies; zero accumulators
    round_weights_kernel<<<248, 256>>>(t_fc_w, g_fc_w, t_wq_w, t_wk_w, t_wv_w,
                                       g_conv_w, fc_w, p_wbuf);
    zero_kernel<<<1, 256>>>(p_red, 2);
    zero_kernel<<<1, 256>>>(p_ksum, HH2);
    zero_kernel<<<64, 256>>>(p_kvs2, HH2 * HH2);

    // ---- Trans + Graph FC (fused over x) ----
    gemm_fc_dual<<<dim3(2, GY), 256, GEMM_SMEM128>>>(
        x, p_wbuf, t_fc_b, t_ln0_g, t_ln0_b, g_fc_b, g_bn0_g, g_bn0_b, p_ht, p_hg);

    // ---- QKV fused (+ norms + ksum in epilogue) ----
    gemm_qkv<<<dim3(6, GY), 256, GEMM_SMEM128>>>(
        p_ht, p_wbuf, t_wq_b, t_wk_b, t_wv_b, p_q, p_k, p_v, p_red, p_ksum);

    // ---- kvs (block-diag accumulate) ----
    {
        const int KC = 704;
        const int SPLITS = (NN + KC - 1) / KC;
        dim3 grid(SPLITS, 2);
        kvs_tf32_kernel<<<grid, 256, KVS_SMEM>>>(p_k, p_v, p_kvs2, KC);
    }
    round_inplace_kernel<<<64, 256>>>(p_kvs2, HH2 * HH2);

    // ---- num GEMM + fused finalize -> x1 ----
    gemm_num_fin<<<dim3(1, GY), 256, GEMM_SMEM256>>>(
        p_q, p_kvs2, p_v, p_ht, p_ksum, p_red, t_ln1_g, t_ln1_b, p_x1);

    // ---- Graph branch (CSR + gather) ----
    zero_int_kernel<<<128, 256>>>(p_cnt, NN);
    deg_int_kernel<<<2048, 256>>>(ei, p_cnt);
    f_kernel<<<128, 256>>>(p_cnt, p_f);
    scan_partial<<<SCAN_NB, 1024>>>(p_cnt, p_bsum);
    scan_bsum<<<1, 128>>>(p_bsum);
    scan_final<<<SCAN_NB, 1024>>>(p_cnt, p_bsum, p_rowptr, p_cursor);
    fill_csr<<<2048, 256>>>(ei, p_cursor, p_csr);
    gather_kernel<<<(NN * 32 + 255) / 256, 256>>>(p_rowptr, p_csr, p_f, p_hg, p_agg);

    // ---- combine + head ----
    gemm_conv_cmb<<<dim3(1, GY), 256, GEMM_SMEM128>>>(
        p_agg, p_wbuf, g_conv_b, g_bn1_g, g_bn1_b, p_hg, p_x1, p_y);

    gemm_out<<<dim3(1, GY), 256, GEMM_SMEM128>>>(p_y, p_wbuf, fc_b, out);
}